// round 7
// baseline (speedup 1.0000x reference)
#include <cuda_runtime.h>
#include <cuda_fp16.h>
#include <math.h>
#include <stdint.h>

// Problem shape (fixed by setup_inputs)
#define MROWS 32768          // B*L
#define BDIM  8
#define LSEQ  4096
#define HD    1024
#define NL    4
#define NCHK  32             // HD / BK

// GEMM tiling: CTA 128x256, 16 warps (4x4), warp tile 32x64, BK=32
#define BM 128
#define BN 256
#define BK 32
#define NSTAGE 5
#define ROWB 80                           // (32+8) fp16 = 80 bytes per row
#define A_STG (BM * ROWB)                 // 10240
#define B_STG (BN * ROWB)                 // 20480
#define STG   (A_STG + B_STG)             // 30720
#define GEMM_SMEM (NSTAGE * STG)          // 153600

// ---------------------------------------------------------------------------
// Scratch (device globals: allocation-free)
// ---------------------------------------------------------------------------
__device__ float g_bufA[(size_t)MROWS * HD];
__device__ float g_bufB[(size_t)MROWS * HD];
__device__ __align__(256) __half g_A2[(size_t)MROWS * HD];    // fp16 A
__device__ __align__(256) __half g_Wt1[(size_t)HD * HD];      // lt_w^T fp16
__device__ __align__(256) __half g_Wt2[(size_t)HD * HD];      // ft_w^T fp16

// ---------------------------------------------------------------------------
// PTX helpers (sm_80-class features only: cp.async, ldmatrix, mma.sync)
// ---------------------------------------------------------------------------
__device__ __forceinline__ uint32_t smem_to_u32(const void* p) {
    uint32_t a;
    asm("{ .reg .u64 t; cvta.to.shared.u64 t, %1; cvt.u32.u64 %0, t; }" : "=r"(a) : "l"(p));
    return a;
}
__device__ __forceinline__ void cp_async16(uint32_t dst, const void* src) {
    asm volatile("cp.async.cg.shared.global [%0], [%1], 16;\n" :: "r"(dst), "l"(src) : "memory");
}
#define CP_COMMIT() asm volatile("cp.async.commit_group;" ::: "memory")
#define CP_WAIT3()  asm volatile("cp.async.wait_group 3;" ::: "memory")

__device__ __forceinline__ void ldsm_x4(uint32_t (&r)[4], uint32_t addr) {
    asm volatile("ldmatrix.sync.aligned.m8n8.x4.shared.b16 {%0,%1,%2,%3}, [%4];"
        : "=r"(r[0]), "=r"(r[1]), "=r"(r[2]), "=r"(r[3]) : "r"(addr));
}
__device__ __forceinline__ void mma16816(float (&c)[4],
                                         const uint32_t (&a)[4],
                                         uint32_t b0, uint32_t b1) {
    asm volatile(
        "mma.sync.aligned.m16n8k16.row.col.f32.f16.f16.f32 "
        "{%0,%1,%2,%3}, {%4,%5,%6,%7}, {%8,%9}, {%0,%1,%2,%3};"
        : "+f"(c[0]), "+f"(c[1]), "+f"(c[2]), "+f"(c[3])
        : "r"(a[0]), "r"(a[1]), "r"(a[2]), "r"(a[3]), "r"(b0), "r"(b1));
}

// full-warp butterfly reduce: every lane ends with the sum
__device__ __forceinline__ float warp_sum(float v) {
    #pragma unroll
    for (int o = 16; o > 0; o >>= 1) v += __shfl_xor_sync(0xffffffffu, v, o);
    return v;
}

// ---------------------------------------------------------------------------
// fp32 -> fp16 conversion of A [M, HD]
// ---------------------------------------------------------------------------
__global__ __launch_bounds__(256) void convA_kernel(
    const float* __restrict__ A, __half* __restrict__ A2)
{
    const size_t i = (size_t)blockIdx.x * 256 + threadIdx.x;
    const float4 v = *(const float4*)(A + i * 4);
    __half h[4];
    h[0] = __float2half_rn(v.x); h[1] = __float2half_rn(v.y);
    h[2] = __float2half_rn(v.z); h[3] = __float2half_rn(v.w);
    ((unsigned long long*)A2)[i] = *(const unsigned long long*)h;
}

// W[HD,HD] fp32 -> Wt[n][k] fp16 (transposed)
__global__ __launch_bounds__(256) void convW_kernel(
    const float* __restrict__ W, __half* __restrict__ Wt)
{
    const int idx = blockIdx.x * 256 + threadIdx.x;   // HD*HD threads
    const int n = idx & (HD - 1);
    const int k = idx >> 10;
    Wt[(size_t)n * HD + k] = __float2half_rn(W[(size_t)k * HD + n]);
}

// ---------------------------------------------------------------------------
// mma.sync GEMM: C[M,HD] = A2[M,HD](f16) x Wt[HD,HD](f16,K-major)^T + bias
// CTA 128x256, 16 warps (4x4), warp tile 32x64, BK=32, 5-stage cp.async.
// ---------------------------------------------------------------------------
__global__ __launch_bounds__(512, 1) void gemm_mma_kernel(
    const __half* __restrict__ A2,
    const __half* __restrict__ Wt,
    const float* __restrict__ bias,
    float* __restrict__ C)
{
    extern __shared__ char smem_raw[];
    const uint32_t sbase = smem_to_u32(smem_raw);

    const int tid = threadIdx.x;
    const int wid = tid >> 5;
    const int lane = tid & 31;
    const int m0 = blockIdx.y * BM;
    const int n0 = blockIdx.x * BN;

    const int wm = (wid >> 2) * 32;      // warp M offset (0..96)
    const int wn = (wid & 3) * 64;       // warp N offset (0..192)

    // ---- global load addressing: per thread 1 A-chunk + 2 B-chunks (16B) ----
    const int lr = tid >> 2;             // 0..127
    const int lc = tid & 3;              // 16B chunk within 64B row
    const __half* gA  = A2 + (size_t)(m0 + lr) * HD + lc * 8;
    const __half* gB0 = Wt + (size_t)(n0 + lr) * HD + lc * 8;
    const __half* gB1 = gB0 + (size_t)128 * HD;

    const uint32_t sA_off = lr * ROWB + lc * 16;
    const uint32_t sB_off = A_STG + lr * ROWB + lc * 16;
    const uint32_t RSTEP128 = 128 * ROWB;   // 128 rows = 10240 B

    // ---- ldmatrix addressing (per lane) ----
    const int lrow = lane & 15;
    const int lkof = (lane >> 4) * 16;
    const uint32_t aAddrBase = sbase + (wm + lrow) * ROWB + lkof;
    const uint32_t bAddrBase = sbase + A_STG + (wn + lrow) * ROWB + lkof;

    float acc[2][8][4];
    #pragma unroll
    for (int i = 0; i < 2; ++i)
        #pragma unroll
        for (int j = 0; j < 8; ++j)
            #pragma unroll
            for (int q = 0; q < 4; ++q) acc[i][j][q] = 0.0f;

    // ---- pipeline prologue: chunks 0..3 into stages 0..3 ----
    #pragma unroll
    for (int p = 0; p < 4; ++p) {
        const uint32_t sb = sbase + p * STG;
        const size_t go = (size_t)p * BK;
        cp_async16(sb + sA_off,            gA  + go);
        cp_async16(sb + sB_off,            gB0 + go);
        cp_async16(sb + sB_off + RSTEP128, gB1 + go);
        CP_COMMIT();
    }

    int s_c = 0;   // stage of chunk kc
    int s_q = 4;   // stage of chunk kc+4
    #pragma unroll 1
    for (int kc = 0; kc < NCHK; ++kc) {
        CP_WAIT3();               // chunk kc landed (<=3 younger outstanding)
        __syncthreads();

        // issue loads for chunk kc+4 (stage held chunk kc-1, done by all warps)
        const int q = kc + 4;
        if (q < NCHK) {
            const uint32_t sb = sbase + s_q * STG;
            const size_t go = (size_t)q * BK;
            cp_async16(sb + sA_off,            gA  + go);
            cp_async16(sb + sB_off,            gB0 + go);
            cp_async16(sb + sB_off + RSTEP128, gB1 + go);
        }
        CP_COMMIT();

        const uint32_t stg = s_c * STG;
        #pragma unroll
        for (int ks = 0; ks < 2; ++ks) {
            uint32_t a[2][4], b[4][4];
            const uint32_t kb = stg + ks * 32;           // 16 fp16 = 32 bytes
            #pragma unroll
            for (int i = 0; i < 2; ++i)
                ldsm_x4(a[i], aAddrBase + kb + i * (16 * ROWB));
            #pragma unroll
            for (int j = 0; j < 4; ++j)
                ldsm_x4(b[j], bAddrBase + kb + j * (16 * ROWB));
            #pragma unroll
            for (int i = 0; i < 2; ++i) {
                #pragma unroll
                for (int j = 0; j < 4; ++j) {
                    mma16816(acc[i][2 * j + 0], a[i], b[j][0], b[j][2]);
                    mma16816(acc[i][2 * j + 1], a[i], b[j][1], b[j][3]);
                }
            }
        }

        if (++s_c == NSTAGE) s_c = 0;
        if (++s_q == NSTAGE) s_q = 0;
    }

    // ---- epilogue: bias add + store ----
    const int g = lane >> 2;             // 0..7
    const int t = lane & 3;              // 0..3
    #pragma unroll
    for (int i = 0; i < 2; ++i) {
        const int row = m0 + wm + i * 16 + g;
        #pragma unroll
        for (int j = 0; j < 8; ++j) {
            const int col = n0 + wn + j * 8 + t * 2;
            const float b0 = bias[col], b1 = bias[col + 1];
            float2 v0 = make_float2(acc[i][j][0] + b0, acc[i][j][1] + b1);
            float2 v1 = make_float2(acc[i][j][2] + b0, acc[i][j][3] + b1);
            *(float2*)(C + (size_t)row * HD + col) = v0;
            *(float2*)(C + (size_t)(row + 8) * HD + col) = v1;
        }
    }
}

// ---------------------------------------------------------------------------
// LN1 + hierarchical fusion: one WARP per row (8 rows per 256-thread block)
// ---------------------------------------------------------------------------
__global__ __launch_bounds__(256) void ln1_fusion_kernel(
    const float* __restrict__ Y, const float* __restrict__ masks,
    const float* __restrict__ emb,
    const float* __restrict__ g, const float* __restrict__ bvec,
    float* __restrict__ Fout)
{
    __shared__ float s_emb[NL * HD];

    const int lane = threadIdx.x & 31;
    const int warp = threadIdx.x >> 5;
    const int row  = blockIdx.x * 8 + warp;

    for (int i = threadIdx.x; i < NL * HD; i += 256) s_emb[i] = emb[i];
    __syncthreads();

    const float* Yr = Y + (size_t)row * HD;

    // load 32 elements per lane (8 x float4, stride 512B)
    float4 y[8];
    float s = 0.f, sq = 0.f;
    #pragma unroll
    for (int ch = 0; ch < 8; ++ch) {
        y[ch] = *(const float4*)(Yr + ch * 128 + lane * 4);
        s  += y[ch].x + y[ch].y + y[ch].z + y[ch].w;
        sq += y[ch].x * y[ch].x + y[ch].y * y[ch].y
            + y[ch].z * y[ch].z + y[ch].w * y[ch].w;
    }
    const float sum   = warp_sum(s);
    const float sumsq = warp_sum(sq);
    const float mu   = sum * (1.0f / HD);
    const float var  = sumsq * (1.0f / HD) - mu * mu;
    const float rstd = rsqrtf(var + 1e-5f);

    // t = LN(y); overwrite y in place; accumulate per-level dot products
    float p0 = 0.f, p1 = 0.f, p2 = 0.f, p3 = 0.f;
    #pragma unroll
    for (int ch = 0; ch < 8; ++ch) {
        const int c = ch * 128 + lane * 4;
        const float4 gv = *(const float4*)(g + c);
        const float4 bv = *(const float4*)(bvec + c);
        y[ch].x = (y[ch].x - mu) * rstd * gv.x + bv.x;
        y[ch].y = (y[ch].y - mu) * rstd * gv.y + bv.y;
        y[ch].z = (y[ch].z - mu) * rstd * gv.z + bv.z;
        y[ch].w = (y[ch].w - mu) * rstd * gv.w + bv.w;
        #pragma unroll
        for (int n = 0; n < NL; ++n) {
            const float4 e = *(const float4*)(s_emb + n * HD + c);
            const float d = y[ch].x * e.x + y[ch].y * e.y
                          + y[ch].z * e.z + y[ch].w * e.w;
            if (n == 0) p0 += d; else if (n == 1) p1 += d;
            else if (n == 2) p2 += d; else p3 += d;
        }
    }
    const float sc0 = warp_sum(p0), sc1 = warp_sum(p1);
    const float sc2 = warp_sum(p2), sc3 = warp_sum(p3);

    const float4 mk = *(const float4*)(masks + (size_t)row * 4);
    const float wn0 = (mk.x > 0.5f) ? expf(sc0) : 0.0f;
    const float wn1 = (mk.y > 0.5f) ? expf(sc1) : 0.0f;
    const float wn2 = (mk.z > 0.5f) ? expf(sc2) : 0.0f;
    const float wn3 = (mk.w > 0.5f) ? expf(sc3) : 0.0f;
    const float tot = wn0 + wn1 + wn2 + wn3;
    const float inv = (tot > 1e-8f) ? (1.0f / tot) : 1.0f;
    const float q0 = wn0 * inv, q1 = wn1 * inv, q2 = wn2 * inv, q3 = wn3 * inv;

    // gate dot: fused . t
    float gd = 0.f;
    #pragma unroll
    for (int ch = 0; ch < 8; ++ch) {
        const int c = ch * 128 + lane * 4;
        const float4 e0 = *(const float4*)(s_emb + 0 * HD + c);
        const float4 e1 = *(const float4*)(s_emb + 1 * HD + c);
        const float4 e2 = *(const float4*)(s_emb + 2 * HD + c);
        const float4 e3 = *(const float4*)(s_emb + 3 * HD + c);
        const float fx = q0 * e0.x + q1 * e1.x + q2 * e2.x + q3 * e3.x;
        const float fy = q0 * e0.y + q1 * e1.y + q2 * e2.y + q3 * e3.y;
        const float fz = q0 * e0.z + q1 * e1.z + q2 * e2.z + q3 * e3.z;
        const float fw = q0 * e0.w + q1 * e1.w + q2 * e2.w + q3 * e3.w;
        gd += fx * y[ch].x + fy * y[ch].y + fz * y[ch].z + fw * y[ch].w;
    }
    const float gsum = warp_sum(gd);
    const float gate = 1.0f / (1.0f + expf(-gsum * (1.0f / HD)));
    const float og = 1.0f - gate;

    float* Fr = Fout + (size_t)row * HD;
    #pragma unroll
    for (int ch = 0; ch < 8; ++ch) {
        const int c = ch * 128 + lane * 4;
        const float4 e0 = *(const float4*)(s_emb + 0 * HD + c);
        const float4 e1 = *(const float4*)(s_emb + 1 * HD + c);
        const float4 e2 = *(const float4*)(s_emb + 2 * HD + c);
        const float4 e3 = *(const float4*)(s_emb + 3 * HD + c);
        float4 o;
        o.x = gate * (q0 * e0.x + q1 * e1.x + q2 * e2.x + q3 * e3.x) + og * y[ch].x;
        o.y = gate * (q0 * e0.y + q1 * e1.y + q2 * e2.y + q3 * e3.y) + og * y[ch].y;
        o.z = gate * (q0 * e0.z + q1 * e1.z + q2 * e2.z + q3 * e3.z) + og * y[ch].z;
        o.w = gate * (q0 * e0.w + q1 * e1.w + q2 * e2.w + q3 * e3.w) + og * y[ch].w;
        *(float4*)(Fr + c) = o;
    }
}

// ---------------------------------------------------------------------------
// Multi-scale windowed means along L (scales 1,3,7,15), fp16 output for GEMM2
// ---------------------------------------------------------------------------
__global__ __launch_bounds__(256) void multiscale_kernel(
    const float* __restrict__ F, __half* __restrict__ A2)
{
    const int L = LSEQ, H = HD;
    const int SL = 128;

    const int gtid = blockIdx.x * 256 + threadIdx.x;
    const int h = gtid & (H - 1);
    const int rest = gtid >> 10;
    const int b = rest & 7;
    const int strip = rest >> 3;
    const int s0 = strip * SL;

    const float* base = F + (size_t)b * L * H + h;
    __half* oA = A2 + (size_t)b * L * H + h;

    const float SW3  = (float)(1.0 / (1.0 + 1.0986122886681098));
    const float SW7  = (float)(1.0 / (1.0 + 1.9459101090932196));
    const float SW15 = (float)(1.0 / (1.0 + 2.7080502011022101));

    if (strip > 0 && strip < 31) {
        float ring[16];
        #pragma unroll
        for (int j = -8; j <= 6; ++j)
            ring[j & 15] = base[(size_t)(s0 + j) * H];

        float s3 = 0.f, s7 = 0.f, s15 = 0.f;
        #pragma unroll
        for (int j = -8; j <= 6; ++j) {
            const float v = ring[j & 15];
            const int d = j + 1;
            if (d >= -7 && d <= 7) s15 += v;
            if (d >= -3 && d <= 3) s7  += v;
            if (d >= -1 && d <= 1) s3  += v;
        }

        const float w3 = SW3 * (1.0f / 3.0f);
        const float w7 = SW7 * (1.0f / 7.0f);
        const float w15 = SW15 * (1.0f / 15.0f);

        #pragma unroll 1
        for (int cch = 0; cch < SL; cch += 16) {
            #pragma unroll
            for (int i = 0; i < 16; ++i) {
                const int l = s0 + cch + i;
                const float nv = base[(size_t)(l + 7) * H];
                ring[(i + 7) & 15] = nv;
                s3  += ring[(i + 1) & 15] - ring[(i - 2) & 15];
                s7  += ring[(i + 3) & 15] - ring[(i - 4) & 15];
                s15 += nv               - ring[(i - 8) & 15];
                const float s1 = ring[i & 15];
                oA[(size_t)l * H] = __float2half_rn(s1 + s3 * w3 + s7 * w7 + s15 * w15);
            }
        }
    } else {
        for (int l = s0; l < s0 + SL; ++l) {
            float s3 = 0.f, s7 = 0.f, s15 = 0.f;
            #pragma unroll
            for (int j = -7; j <= 7; ++j) {
                const int p = l + j;
                const float v = (p >= 0 && p < L) ? base[(size_t)p * H] : 0.0f;
                s15 += v;
                if (j >= -3 && j <= 3) s7 += v;
                if (j >= -1 && j <= 1) s3 += v;
            }
            const float s1 = base[(size_t)l * H];
            const int cnt3  = min(l + 2, L) - max(l - 1, 0);
            const int cnt7  = min(l + 4, L) - max(l - 3, 0);
            const int cnt15 = min(l + 8, L) - max(l - 7, 0);
            const float outv = s1
                + SW3  * s3  / (float)cnt3
                + SW7  * s7  / (float)cnt7
                + SW15 * s15 / (float)cnt15;
            oA[(size_t)l * H] = __float2half_rn(outv);
        }
    }
}

// ---------------------------------------------------------------------------
// LN2 + residual: one WARP per row
// ---------------------------------------------------------------------------
__global__ __launch_bounds__(256) void ln2_res_kernel(
    const float* __restrict__ Y, const float* __restrict__ X,
    const float* __restrict__ g, const float* __restrict__ bvec,
    float* __restrict__ out)
{
    const int lane = threadIdx.x & 31;
    const int warp = threadIdx.x >> 5;
    const int row  = blockIdx.x * 8 + warp;

    const float* Yr = Y + (size_t)row * HD;

    float4 y[8];
    float s = 0.f, sq = 0.f;
    #pragma unroll
    for (int ch = 0; ch < 8; ++ch) {
        y[ch] = *(const float4*)(Yr + ch * 128 + lane * 4);
        s  += y[ch].x + y[ch].y + y[ch].z + y[ch].w;
        sq += y[ch].x * y[ch].x + y[ch].y * y[ch].y
            + y[ch].z * y[ch].z + y[ch].w * y[ch].w;
    }
    const float sum   = warp_sum(s);
    const float sumsq = warp_sum(sq);
    const float mu   = sum * (1.0f / HD);
    const float var  = sumsq * (1.0f / HD) - mu * mu;
    const float rstd = rsqrtf(var + 1e-5f);

    const float* Xr = X + (size_t)row * HD;
    float* Or = out + (size_t)row * HD;
    #pragma unroll
    for (int ch = 0; ch < 8; ++ch) {
        const int c = ch * 128 + lane * 4;
        const float4 gv = *(const float4*)(g + c);
        const float4 bv = *(const float4*)(bvec + c);
        const float4 xv = *(const float4*)(Xr + c);
        float4 o;
        o.x = (y[ch].x - mu) * rstd * gv.x + bv.x + xv.x;
        o.y = (y[ch].y - mu) * rstd * gv.y + bv.y + xv.y;
        o.z = (y[ch].z - mu) * rstd * gv.z + bv.z + xv.z;
        o.w = (y[ch].w - mu) * rstd * gv.w + bv.w + xv.w;
        *(float4*)(Or + c) = o;
    }
}

// ---------------------------------------------------------------------------
// Launcher
// ---------------------------------------------------------------------------
extern "C" void kernel_launch(void* const* d_in, const int* in_sizes, int n_in,
                              void* d_out, int out_size)
{
    const float* X   = (const float*)d_in[0];
    const float* msk = (const float*)d_in[1];
    const float* emb = (const float*)d_in[2];
    const float* ltw = (const float*)d_in[3];
    const float* ltb = (const float*)d_in[4];
    const float* g1  = (const float*)d_in[5];
    const float* b1  = (const float*)d_in[6];
    const float* ftw = (const float*)d_in[7];
    const float* ftb = (const float*)d_in[8];
    const float* g2  = (const float*)d_in[9];
    const float* b2  = (const float*)d_in[10];
    float* out = (float*)d_out;

    float *bufA, *bufB;
    __half *A2, *Wt1, *Wt2;
    cudaGetSymbolAddress((void**)&bufA, g_bufA);
    cudaGetSymbolAddress((void**)&bufB, g_bufB);
    cudaGetSymbolAddress((void**)&A2,  g_A2);
    cudaGetSymbolAddress((void**)&Wt1, g_Wt1);
    cudaGetSymbolAddress((void**)&Wt2, g_Wt2);

    cudaFuncSetAttribute((const void*)gemm_mma_kernel,
                         cudaFuncAttributeMaxDynamicSharedMemorySize, GEMM_SMEM);

    const dim3 ggrid(HD / BN, MROWS / BM);   // (4, 256)

    // weight transposes to fp16 (every call; deterministic)
    convW_kernel<<<(HD * HD) / 256, 256>>>(ltw, Wt1);
    convW_kernel<<<(HD * HD) / 256, 256>>>(ftw, Wt2);

    // 1) Y1 = X @ lt_w + lt_b
    convA_kernel<<<(MROWS * HD / 4) / 256, 256>>>(X, A2);
    gemm_mma_kernel<<<ggrid, 512, GEMM_SMEM>>>(A2, Wt1, ltb, bufA);
    // 2) F = fusion(LN1(Y1))
    ln1_fusion_kernel<<<MROWS / 8, 256>>>(bufA, msk, emb, g1, b1, bufB);
    // 3) agg = multiscale(F), fp16 out -> A2
    multiscale_kernel<<<(BDIM * HD * 32) / 256, 256>>>(bufB, A2);
    // 4) Y2 = agg @ ft_w + ft_b
    gemm_mma_kernel<<<ggrid, 512, GEMM_SMEM>>>(A2, Wt2, ftb, bufA);
    // 5) out = LN2(Y2) + X
    ln2_res_kernel<<<MROWS / 8, 256>>>(bufA, X, g2, b2, out);
}

// round 8
// speedup vs baseline: 1.3203x; 1.3203x over previous
#include <cuda_runtime.h>
#include <cuda_fp16.h>
#include <math.h>
#include <stdint.h>

// Problem shape (fixed by setup_inputs)
#define MROWS 32768          // B*L
#define BDIM  8
#define LSEQ  4096
#define HD    1024
#define NL    4
#define NCHK  32             // HD / BK

// GEMM tiling: CTA 128x128, 4 warps (2x2), warp tile 64x64, BK=32
#define BM 128
#define BN 128
#define BK 32
#define NSTAGE 5
#define ROWB 80                           // (32+8) fp16 = 80 bytes per row
#define A_STG (BM * ROWB)                 // 10240
#define B_STG (BN * ROWB)                 // 10240
#define STG   (A_STG + B_STG)             // 20480
#define GEMM_SMEM (NSTAGE * STG)          // 102400  (x2 CTAs = 200KB < 228KB)

// ---------------------------------------------------------------------------
// Scratch (device globals: allocation-free)
// ---------------------------------------------------------------------------
__device__ float g_bufA[(size_t)MROWS * HD];
__device__ float g_bufB[(size_t)MROWS * HD];
__device__ __align__(256) __half g_A2[(size_t)MROWS * HD];    // fp16 A
__device__ __align__(256) __half g_Wt1[(size_t)HD * HD];      // lt_w^T fp16
__device__ __align__(256) __half g_Wt2[(size_t)HD * HD];      // ft_w^T fp16

// ---------------------------------------------------------------------------
// PTX helpers (sm_80-class features only: cp.async, ldmatrix, mma.sync)
// ---------------------------------------------------------------------------
__device__ __forceinline__ uint32_t smem_to_u32(const void* p) {
    uint32_t a;
    asm("{ .reg .u64 t; cvta.to.shared.u64 t, %1; cvt.u32.u64 %0, t; }" : "=r"(a) : "l"(p));
    return a;
}
__device__ __forceinline__ void cp_async16(uint32_t dst, const void* src) {
    asm volatile("cp.async.cg.shared.global [%0], [%1], 16;\n" :: "r"(dst), "l"(src) : "memory");
}
#define CP_COMMIT() asm volatile("cp.async.commit_group;" ::: "memory")
#define CP_WAIT3()  asm volatile("cp.async.wait_group 3;" ::: "memory")

__device__ __forceinline__ void ldsm_x4(uint32_t (&r)[4], uint32_t addr) {
    asm volatile("ldmatrix.sync.aligned.m8n8.x4.shared.b16 {%0,%1,%2,%3}, [%4];"
        : "=r"(r[0]), "=r"(r[1]), "=r"(r[2]), "=r"(r[3]) : "r"(addr));
}
__device__ __forceinline__ void mma16816(float (&c)[4],
                                         const uint32_t (&a)[4],
                                         uint32_t b0, uint32_t b1) {
    asm volatile(
        "mma.sync.aligned.m16n8k16.row.col.f32.f16.f16.f32 "
        "{%0,%1,%2,%3}, {%4,%5,%6,%7}, {%8,%9}, {%0,%1,%2,%3};"
        : "+f"(c[0]), "+f"(c[1]), "+f"(c[2]), "+f"(c[3])
        : "r"(a[0]), "r"(a[1]), "r"(a[2]), "r"(a[3]), "r"(b0), "r"(b1));
}

// ---------------------------------------------------------------------------
// fp32 -> fp16 conversion of A [M, HD]
// ---------------------------------------------------------------------------
__global__ __launch_bounds__(256) void convA_kernel(
    const float* __restrict__ A, __half* __restrict__ A2)
{
    const size_t i = (size_t)blockIdx.x * 256 + threadIdx.x;
    const float4 v = *(const float4*)(A + i * 4);
    __half h[4];
    h[0] = __float2half_rn(v.x); h[1] = __float2half_rn(v.y);
    h[2] = __float2half_rn(v.z); h[3] = __float2half_rn(v.w);
    ((unsigned long long*)A2)[i] = *(const unsigned long long*)h;
}

// W[HD,HD] fp32 -> Wt[n][k] fp16 (transposed)
__global__ __launch_bounds__(256) void convW_kernel(
    const float* __restrict__ W, __half* __restrict__ Wt)
{
    const int idx = blockIdx.x * 256 + threadIdx.x;   // HD*HD threads
    const int n = idx & (HD - 1);
    const int k = idx >> 10;
    Wt[(size_t)n * HD + k] = __float2half_rn(W[(size_t)k * HD + n]);
}

// ---------------------------------------------------------------------------
// mma.sync GEMM: C[M,HD] = A2[M,HD](f16) x Wt[HD,HD](f16,K-major)^T + bias
// CTA 128x128, 4 warps (2x2), warp tile 64x64, BK=32, 5-stage cp.async.
// 2 CTAs co-resident per SM: independent barriers overlap each other's stalls.
// ---------------------------------------------------------------------------
__global__ __launch_bounds__(128, 2) void gemm_mma_kernel(
    const __half* __restrict__ A2,
    const __half* __restrict__ Wt,
    const float* __restrict__ bias,
    float* __restrict__ C)
{
    extern __shared__ char smem_raw[];
    const uint32_t sbase = smem_to_u32(smem_raw);

    const int tid = threadIdx.x;
    const int wid = tid >> 5;
    const int lane = tid & 31;
    const int m0 = blockIdx.y * BM;
    const int n0 = blockIdx.x * BN;

    const int wm = (wid >> 1) * 64;      // warp M offset (0/64)
    const int wn = (wid & 1) * 64;       // warp N offset (0/64)

    // ---- global load addressing: per thread 4 A-chunks + 4 B-chunks (16B) ----
    const int lr = tid >> 2;             // 0..31
    const int lc = tid & 3;              // 16B chunk within 64B row
    const __half* gA[4];
    const __half* gB[4];
    #pragma unroll
    for (int j = 0; j < 4; ++j) {
        gA[j] = A2 + (size_t)(m0 + lr + 32 * j) * HD + lc * 8;
        gB[j] = Wt + (size_t)(n0 + lr + 32 * j) * HD + lc * 8;
    }
    const uint32_t sA_off = lr * ROWB + lc * 16;
    const uint32_t sB_off = A_STG + lr * ROWB + lc * 16;
    const uint32_t RSTEP32 = 32 * ROWB;  // 32 rows = 2560 B

    // ---- ldmatrix addressing (per lane) ----
    const int lrow = lane & 15;
    const int lkof = (lane >> 4) * 16;
    const uint32_t aAddrBase = sbase + (wm + lrow) * ROWB + lkof;
    const uint32_t bAddrBase = sbase + A_STG + (wn + lrow) * ROWB + lkof;

    float acc[4][8][4];
    #pragma unroll
    for (int i = 0; i < 4; ++i)
        #pragma unroll
        for (int j = 0; j < 8; ++j)
            #pragma unroll
            for (int q = 0; q < 4; ++q) acc[i][j][q] = 0.0f;

    // ---- pipeline prologue: chunks 0..3 into stages 0..3 ----
    #pragma unroll
    for (int p = 0; p < 4; ++p) {
        const uint32_t sb = sbase + p * STG;
        const size_t go = (size_t)p * BK;
        #pragma unroll
        for (int j = 0; j < 4; ++j) {
            cp_async16(sb + sA_off + j * RSTEP32, gA[j] + go);
            cp_async16(sb + sB_off + j * RSTEP32, gB[j] + go);
        }
        CP_COMMIT();
    }

    int s_c = 0;   // stage of chunk kc
    int s_q = 4;   // stage of chunk kc+4
    #pragma unroll 1
    for (int kc = 0; kc < NCHK; ++kc) {
        CP_WAIT3();               // chunk kc landed (<=3 younger outstanding)
        __syncthreads();

        // issue loads for chunk kc+4 (stage held chunk kc-1, done by all warps)
        const int q = kc + 4;
        if (q < NCHK) {
            const uint32_t sb = sbase + s_q * STG;
            const size_t go = (size_t)q * BK;
            #pragma unroll
            for (int j = 0; j < 4; ++j) {
                cp_async16(sb + sA_off + j * RSTEP32, gA[j] + go);
                cp_async16(sb + sB_off + j * RSTEP32, gB[j] + go);
            }
        }
        CP_COMMIT();

        const uint32_t stg = s_c * STG;
        // load BOTH ks-halves' fragments up front, then back-to-back MMA
        uint32_t a0[4][4], b0[4][4], a1[4][4], b1[4][4];
        #pragma unroll
        for (int i = 0; i < 4; ++i)
            ldsm_x4(a0[i], aAddrBase + stg + i * (16 * ROWB));
        #pragma unroll
        for (int j = 0; j < 4; ++j)
            ldsm_x4(b0[j], bAddrBase + stg + j * (16 * ROWB));
        #pragma unroll
        for (int i = 0; i < 4; ++i)
            ldsm_x4(a1[i], aAddrBase + stg + 32 + i * (16 * ROWB));
        #pragma unroll
        for (int j = 0; j < 4; ++j)
            ldsm_x4(b1[j], bAddrBase + stg + 32 + j * (16 * ROWB));

        #pragma unroll
        for (int i = 0; i < 4; ++i) {
            #pragma unroll
            for (int j = 0; j < 4; ++j) {
                mma16816(acc[i][2 * j + 0], a0[i], b0[j][0], b0[j][2]);
                mma16816(acc[i][2 * j + 1], a0[i], b0[j][1], b0[j][3]);
            }
        }
        #pragma unroll
        for (int i = 0; i < 4; ++i) {
            #pragma unroll
            for (int j = 0; j < 4; ++j) {
                mma16816(acc[i][2 * j + 0], a1[i], b1[j][0], b1[j][2]);
                mma16816(acc[i][2 * j + 1], a1[i], b1[j][1], b1[j][3]);
            }
        }

        if (++s_c == NSTAGE) s_c = 0;
        if (++s_q == NSTAGE) s_q = 0;
    }

    // ---- epilogue: bias add + store ----
    const int g = lane >> 2;             // 0..7
    const int t = lane & 3;              // 0..3
    #pragma unroll
    for (int i = 0; i < 4; ++i) {
        const int row = m0 + wm + i * 16 + g;
        #pragma unroll
        for (int j = 0; j < 8; ++j) {
            const int col = n0 + wn + j * 8 + t * 2;
            const float b0 = bias[col], b1 = bias[col + 1];
            float2 v0 = make_float2(acc[i][j][0] + b0, acc[i][j][1] + b1);
            float2 v1 = make_float2(acc[i][j][2] + b0, acc[i][j][3] + b1);
            *(float2*)(C + (size_t)row * HD + col) = v0;
            *(float2*)(C + (size_t)(row + 8) * HD + col) = v1;
        }
    }
}

// ---------------------------------------------------------------------------
// Block reduction helper (256 threads)
// ---------------------------------------------------------------------------
__device__ __forceinline__ float blk_reduce(float v, float* sbuf)
{
    #pragma unroll
    for (int o = 16; o > 0; o >>= 1) v += __shfl_down_sync(0xffffffffu, v, o);
    const int lane = threadIdx.x & 31;
    const int w = threadIdx.x >> 5;
    if (lane == 0) sbuf[w] = v;
    __syncthreads();
    if (threadIdx.x < 32) {
        float x = (threadIdx.x < 8) ? sbuf[threadIdx.x] : 0.0f;
        #pragma unroll
        for (int o = 4; o > 0; o >>= 1) x += __shfl_down_sync(0xffffffffu, x, o);
        if (threadIdx.x == 0) sbuf[0] = x;
    }
    __syncthreads();
    float r = sbuf[0];
    __syncthreads();
    return r;
}

// ---------------------------------------------------------------------------
// LN1 + hierarchical fusion (one block per row)
// ---------------------------------------------------------------------------
__global__ __launch_bounds__(256) void ln1_fusion_kernel(
    const float* __restrict__ Y, const float* __restrict__ masks,
    const float* __restrict__ emb,
    const float* __restrict__ g, const float* __restrict__ bvec,
    float* __restrict__ Fout)
{
    __shared__ float s_emb[NL * HD];
    __shared__ float sbuf[8];

    const int row = blockIdx.x;
    const int c = threadIdx.x * 4;

    for (int i = threadIdx.x; i < NL * HD; i += 256) s_emb[i] = emb[i];
    __syncthreads();

    const float4 y = *(const float4*)(Y + (size_t)row * HD + c);
    float s  = y.x + y.y + y.z + y.w;
    float sq = y.x * y.x + y.y * y.y + y.z * y.z + y.w * y.w;
    const float sum   = blk_reduce(s, sbuf);
    const float sumsq = blk_reduce(sq, sbuf);
    const float mu   = sum * (1.0f / HD);
    const float var  = sumsq * (1.0f / HD) - mu * mu;
    const float rstd = rsqrtf(var + 1e-5f);

    const float4 gv = *(const float4*)(g + c);
    const float4 bv = *(const float4*)(bvec + c);
    const float t0 = (y.x - mu) * rstd * gv.x + bv.x;
    const float t1 = (y.y - mu) * rstd * gv.y + bv.y;
    const float t2 = (y.z - mu) * rstd * gv.z + bv.z;
    const float t3 = (y.w - mu) * rstd * gv.w + bv.w;

    float sc[NL];
    #pragma unroll
    for (int n = 0; n < NL; ++n) {
        const float* e = s_emb + n * HD + c;
        float p = t0 * e[0] + t1 * e[1] + t2 * e[2] + t3 * e[3];
        sc[n] = blk_reduce(p, sbuf);
    }

    const float4 mk = *(const float4*)(masks + (size_t)row * 4);
    float wn0 = (mk.x > 0.5f) ? expf(sc[0]) : 0.0f;
    float wn1 = (mk.y > 0.5f) ? expf(sc[1]) : 0.0f;
    float wn2 = (mk.z > 0.5f) ? expf(sc[2]) : 0.0f;
    float wn3 = (mk.w > 0.5f) ? expf(sc[3]) : 0.0f;
    const float tot = wn0 + wn1 + wn2 + wn3;
    const float inv = (tot > 1e-8f) ? (1.0f / tot) : 1.0f;

    const float* e0 = s_emb + 0 * HD + c;
    const float* e1 = s_emb + 1 * HD + c;
    const float* e2 = s_emb + 2 * HD + c;
    const float* e3 = s_emb + 3 * HD + c;
    const float f0 = (wn0 * e0[0] + wn1 * e1[0] + wn2 * e2[0] + wn3 * e3[0]) * inv;
    const float f1 = (wn0 * e0[1] + wn1 * e1[1] + wn2 * e2[1] + wn3 * e3[1]) * inv;
    const float f2 = (wn0 * e0[2] + wn1 * e1[2] + wn2 * e2[2] + wn3 * e3[2]) * inv;
    const float f3 = (wn0 * e0[3] + wn1 * e1[3] + wn2 * e2[3] + wn3 * e3[3]) * inv;

    const float gd = f0 * t0 + f1 * t1 + f2 * t2 + f3 * t3;
    const float gsum = blk_reduce(gd, sbuf);
    const float gate = 1.0f / (1.0f + expf(-gsum * (1.0f / HD)));
    const float og = 1.0f - gate;

    float4 o;
    o.x = gate * f0 + og * t0;
    o.y = gate * f1 + og * t1;
    o.z = gate * f2 + og * t2;
    o.w = gate * f3 + og * t3;
    *(float4*)(Fout + (size_t)row * HD + c) = o;
}

// ---------------------------------------------------------------------------
// Multi-scale windowed means along L (scales 1,3,7,15), fp16 output for GEMM2
// ---------------------------------------------------------------------------
__global__ __launch_bounds__(256) void multiscale_kernel(
    const float* __restrict__ F, __half* __restrict__ A2)
{
    const int L = LSEQ, H = HD;
    const int SL = 128;

    const int gtid = blockIdx.x * 256 + threadIdx.x;
    const int h = gtid & (H - 1);
    const int rest = gtid >> 10;
    const int b = rest & 7;
    const int strip = rest >> 3;
    const int s0 = strip * SL;

    const float* base = F + (size_t)b * L * H + h;
    __half* oA = A2 + (size_t)b * L * H + h;

    const float SW3  = (float)(1.0 / (1.0 + 1.0986122886681098));
    const float SW7  = (float)(1.0 / (1.0 + 1.9459101090932196));
    const float SW15 = (float)(1.0 / (1.0 + 2.7080502011022101));

    if (strip > 0 && strip < 31) {
        float ring[16];
        #pragma unroll
        for (int j = -8; j <= 6; ++j)
            ring[j & 15] = base[(size_t)(s0 + j) * H];

        float s3 = 0.f, s7 = 0.f, s15 = 0.f;
        #pragma unroll
        for (int j = -8; j <= 6; ++j) {
            const float v = ring[j & 15];
            const int d = j + 1;
            if (d >= -7 && d <= 7) s15 += v;
            if (d >= -3 && d <= 3) s7  += v;
            if (d >= -1 && d <= 1) s3  += v;
        }

        const float w3 = SW3 * (1.0f / 3.0f);
        const float w7 = SW7 * (1.0f / 7.0f);
        const float w15 = SW15 * (1.0f / 15.0f);

        #pragma unroll 1
        for (int cch = 0; cch < SL; cch += 16) {
            #pragma unroll
            for (int i = 0; i < 16; ++i) {
                const int l = s0 + cch + i;
                const float nv = base[(size_t)(l + 7) * H];
                ring[(i + 7) & 15] = nv;
                s3  += ring[(i + 1) & 15] - ring[(i - 2) & 15];
                s7  += ring[(i + 3) & 15] - ring[(i - 4) & 15];
                s15 += nv               - ring[(i - 8) & 15];
                const float s1 = ring[i & 15];
                oA[(size_t)l * H] = __float2half_rn(s1 + s3 * w3 + s7 * w7 + s15 * w15);
            }
        }
    } else {
        for (int l = s0; l < s0 + SL; ++l) {
            float s3 = 0.f, s7 = 0.f, s15 = 0.f;
            #pragma unroll
            for (int j = -7; j <= 7; ++j) {
                const int p = l + j;
                const float v = (p >= 0 && p < L) ? base[(size_t)p * H] : 0.0f;
                s15 += v;
                if (j >= -3 && j <= 3) s7 += v;
                if (j >= -1 && j <= 1) s3 += v;
            }
            const float s1 = base[(size_t)l * H];
            const int cnt3  = min(l + 2, L) - max(l - 1, 0);
            const int cnt7  = min(l + 4, L) - max(l - 3, 0);
            const int cnt15 = min(l + 8, L) - max(l - 7, 0);
            const float outv = s1
                + SW3  * s3  / (float)cnt3
                + SW7  * s7  / (float)cnt7
                + SW15 * s15 / (float)cnt15;
            oA[(size_t)l * H] = __float2half_rn(outv);
        }
    }
}

// ---------------------------------------------------------------------------
// LN2 + residual (one block per row)
// ---------------------------------------------------------------------------
__global__ __launch_bounds__(256) void ln2_res_kernel(
    const float* __restrict__ Y, const float* __restrict__ X,
    const float* __restrict__ g, const float* __restrict__ bvec,
    float* __restrict__ out)
{
    __shared__ float sbuf[8];
    const int row = blockIdx.x;
    const int c = threadIdx.x * 4;

    const float4 y = *(const float4*)(Y + (size_t)row * HD + c);
    float s  = y.x + y.y + y.z + y.w;
    float sq = y.x * y.x + y.y * y.y + y.z * y.z + y.w * y.w;
    const float sum   = blk_reduce(s, sbuf);
    const float sumsq = blk_reduce(sq, sbuf);
    const float mu   = sum * (1.0f / HD);
    const float var  = sumsq * (1.0f / HD) - mu * mu;
    const float rstd = rsqrtf(var + 1e-5f);

    const float4 gv = *(const float4*)(g + c);
    const float4 bv = *(const float4*)(bvec + c);
    const float4 xv = *(const float4*)(X + (size_t)row * HD + c);

    float4 o;
    o.x = (y.x - mu) * rstd * gv.x + bv.x + xv.x;
    o.y = (y.y - mu) * rstd * gv.y + bv.y + xv.y;
    o.z = (y.z - mu) * rstd * gv.z + bv.z + xv.z;
    o.w = (y.w - mu) * rstd * gv.w + bv.w + xv.w;
    *(float4*)(out + (size_t)row * HD + c) = o;
}

// ---------------------------------------------------------------------------
// Launcher
// ---------------------------------------------------------------------------
extern "C" void kernel_launch(void* const* d_in, const int* in_sizes, int n_in,
                              void* d_out, int out_size)
{
    const float* X   = (const float*)d_in[0];
    const float* msk = (const float*)d_in[1];
    const float* emb = (const float*)d_in[2];
    const float* ltw = (const float*)d_in[3];
    const float* ltb = (const float*)d_in[4];
    const float* g1  = (const float*)d_in[5];
    const float* b1  = (const float*)d_in[6];
    const float* ftw = (const float*)d_in[7];
    const float* ftb = (const float*)d_in[8];
    const float* g2  = (const float*)d_in[9];
    const float* b2  = (const float*)d_in[10];
    float* out = (float*)d_out;

    float *bufA, *bufB;
    __half *A2, *Wt1, *Wt2;
    cudaGetSymbolAddress((void**)&bufA, g_bufA);
    cudaGetSymbolAddress((void**)&bufB, g_bufB);
    cudaGetSymbolAddress((void**)&A2,  g_A2);
    cudaGetSymbolAddress((void**)&Wt1, g_Wt1);
    cudaGetSymbolAddress((void**)&Wt2, g_Wt2);

    cudaFuncSetAttribute((const void*)gemm_mma_kernel,
                         cudaFuncAttributeMaxDynamicSharedMemorySize, GEMM_SMEM);

    const dim3 ggrid(HD / BN, MROWS / BM);   // (8, 256) = 2048 CTAs

    // weight transposes to fp16 (every call; deterministic)
    convW_kernel<<<(HD * HD) / 256, 256>>>(ltw, Wt1);
    convW_kernel<<<(HD * HD) / 256, 256>>>(ftw, Wt2);

    // 1) Y1 = X @ lt_w + lt_b
    convA_kernel<<<(MROWS * HD / 4) / 256, 256>>>(X, A2);
    gemm_mma_kernel<<<ggrid, 128, GEMM_SMEM>>>(A2, Wt1, ltb, bufA);
    // 2) F = fusion(LN1(Y1))
    ln1_fusion_kernel<<<MROWS, 256>>>(bufA, msk, emb, g1, b1, bufB);
    // 3) agg = multiscale(F), fp16 out -> A2
    multiscale_kernel<<<(BDIM * HD * 32) / 256, 256>>>(bufB, A2);
    // 4) Y2 = agg @ ft_w + ft_b
    gemm_mma_kernel<<<ggrid, 128, GEMM_SMEM>>>(A2, Wt2, ftb, bufA);
    // 5) out = LN2(Y2) + X
    ln2_res_kernel<<<MROWS, 256>>>(bufA, X, g2, b2, out);
}

// round 9
// speedup vs baseline: 1.4316x; 1.0843x over previous
#include <cuda_runtime.h>
#include <cuda_fp16.h>
#include <math.h>
#include <stdint.h>

// Problem shape (fixed by setup_inputs)
#define MROWS 32768          // B*L
#define BDIM  8
#define LSEQ  4096
#define HD    1024
#define NL    4
#define NCHK  32             // HD / BK

// GEMM tiling: CTA 128x128, 4 warps (2x2), warp tile 64x64, BK=32
#define BM 128
#define BN 128
#define BK 32
#define NSTAGE 5
#define ROWB 80                           // (32+8) fp16 = 80 bytes per row
#define A_STG (BM * ROWB)                 // 10240
#define B_STG (BN * ROWB)                 // 10240
#define STG   (A_STG + B_STG)             // 20480
#define GEMM_SMEM (NSTAGE * STG)          // 102400  (x2 CTAs = 200KB < 228KB)

// ---------------------------------------------------------------------------
// Scratch (device globals: allocation-free)
// ---------------------------------------------------------------------------
__device__ float g_bufA[(size_t)MROWS * HD];
__device__ float g_bufB[(size_t)MROWS * HD];     // low half reused as fp16 F
__device__ __align__(256) __half g_A2[(size_t)MROWS * HD];    // fp16 A
__device__ __align__(256) __half g_Wt1[(size_t)HD * HD];      // lt_w^T fp16
__device__ __align__(256) __half g_Wt2[(size_t)HD * HD];      // ft_w^T fp16

// ---------------------------------------------------------------------------
// PTX helpers (sm_80-class features only: cp.async, ldmatrix, mma.sync)
// ---------------------------------------------------------------------------
__device__ __forceinline__ uint32_t smem_to_u32(const void* p) {
    uint32_t a;
    asm("{ .reg .u64 t; cvta.to.shared.u64 t, %1; cvt.u32.u64 %0, t; }" : "=r"(a) : "l"(p));
    return a;
}
__device__ __forceinline__ void cp_async16(uint32_t dst, const void* src) {
    asm volatile("cp.async.cg.shared.global [%0], [%1], 16;\n" :: "r"(dst), "l"(src) : "memory");
}
#define CP_COMMIT() asm volatile("cp.async.commit_group;" ::: "memory")
#define CP_WAIT3()  asm volatile("cp.async.wait_group 3;" ::: "memory")

__device__ __forceinline__ void ldsm_x4(uint32_t (&r)[4], uint32_t addr) {
    asm volatile("ldmatrix.sync.aligned.m8n8.x4.shared.b16 {%0,%1,%2,%3}, [%4];"
        : "=r"(r[0]), "=r"(r[1]), "=r"(r[2]), "=r"(r[3]) : "r"(addr));
}
__device__ __forceinline__ void mma16816(float (&c)[4],
                                         const uint32_t (&a)[4],
                                         uint32_t b0, uint32_t b1) {
    asm volatile(
        "mma.sync.aligned.m16n8k16.row.col.f32.f16.f16.f32 "
        "{%0,%1,%2,%3}, {%4,%5,%6,%7}, {%8,%9}, {%0,%1,%2,%3};"
        : "+f"(c[0]), "+f"(c[1]), "+f"(c[2]), "+f"(c[3])
        : "r"(a[0]), "r"(a[1]), "r"(a[2]), "r"(a[3]), "r"(b0), "r"(b1));
}

__device__ __forceinline__ float warp_sum(float v) {
    #pragma unroll
    for (int o = 16; o > 0; o >>= 1) v += __shfl_xor_sync(0xffffffffu, v, o);
    return v;
}

// ---- fused block reductions (256 threads, 8 warps), disjoint sbuf regions ----
// dual: slots 0..17
__device__ __forceinline__ void blk_reduce2(float v1, float v2, float* sbuf,
                                            float& r1, float& r2)
{
    v1 = warp_sum(v1); v2 = warp_sum(v2);
    const int lane = threadIdx.x & 31, w = threadIdx.x >> 5;
    if (lane == 0) { sbuf[w] = v1; sbuf[8 + w] = v2; }
    __syncthreads();
    if (threadIdx.x < 16) {
        float x = sbuf[threadIdx.x];
        x += __shfl_xor_sync(0xffffu, x, 4);
        x += __shfl_xor_sync(0xffffu, x, 2);
        x += __shfl_xor_sync(0xffffu, x, 1);
        if ((threadIdx.x & 7) == 0) sbuf[16 + (threadIdx.x >> 3)] = x;
    }
    __syncthreads();
    r1 = sbuf[16]; r2 = sbuf[17];
}

// quad: slots 20..55
__device__ __forceinline__ void blk_reduce4(float p0, float p1, float p2, float p3,
                                            float* sbuf,
                                            float& r0, float& r1, float& r2, float& r3)
{
    p0 = warp_sum(p0); p1 = warp_sum(p1); p2 = warp_sum(p2); p3 = warp_sum(p3);
    const int lane = threadIdx.x & 31, w = threadIdx.x >> 5;
    if (lane == 0) {
        sbuf[20 + w] = p0; sbuf[28 + w] = p1; sbuf[36 + w] = p2; sbuf[44 + w] = p3;
    }
    __syncthreads();
    if (threadIdx.x < 32) {
        float x = sbuf[20 + threadIdx.x];
        x += __shfl_xor_sync(0xffffffffu, x, 4);
        x += __shfl_xor_sync(0xffffffffu, x, 2);
        x += __shfl_xor_sync(0xffffffffu, x, 1);
        if ((threadIdx.x & 7) == 0) sbuf[52 + (threadIdx.x >> 3)] = x;
    }
    __syncthreads();
    r0 = sbuf[52]; r1 = sbuf[53]; r2 = sbuf[54]; r3 = sbuf[55];
}

// single: slots 56..64
__device__ __forceinline__ float blk_reduce1(float v, float* sbuf)
{
    v = warp_sum(v);
    const int lane = threadIdx.x & 31, w = threadIdx.x >> 5;
    if (lane == 0) sbuf[56 + w] = v;
    __syncthreads();
    if (threadIdx.x < 8) {
        float x = sbuf[56 + threadIdx.x];
        x += __shfl_xor_sync(0xffu, x, 4);
        x += __shfl_xor_sync(0xffu, x, 2);
        x += __shfl_xor_sync(0xffu, x, 1);
        if (threadIdx.x == 0) sbuf[64] = x;
    }
    __syncthreads();
    return sbuf[64];
}

// ---------------------------------------------------------------------------
// fp32 -> fp16 conversion of A [M, HD]
// ---------------------------------------------------------------------------
__global__ __launch_bounds__(256) void convA_kernel(
    const float* __restrict__ A, __half* __restrict__ A2)
{
    const size_t i = (size_t)blockIdx.x * 256 + threadIdx.x;
    const float4 v = *(const float4*)(A + i * 4);
    __half h[4];
    h[0] = __float2half_rn(v.x); h[1] = __float2half_rn(v.y);
    h[2] = __float2half_rn(v.z); h[3] = __float2half_rn(v.w);
    ((unsigned long long*)A2)[i] = *(const unsigned long long*)h;
}

// W[HD,HD] fp32 -> Wt[n][k] fp16 (transposed)
__global__ __launch_bounds__(256) void convW_kernel(
    const float* __restrict__ W, __half* __restrict__ Wt)
{
    const int idx = blockIdx.x * 256 + threadIdx.x;   // HD*HD threads
    const int n = idx & (HD - 1);
    const int k = idx >> 10;
    Wt[(size_t)n * HD + k] = __float2half_rn(W[(size_t)k * HD + n]);
}

// ---------------------------------------------------------------------------
// mma.sync GEMM (UNCHANGED from round 8): CTA 128x128, 4 warps, 64x64 tiles.
// ---------------------------------------------------------------------------
__global__ __launch_bounds__(128, 2) void gemm_mma_kernel(
    const __half* __restrict__ A2,
    const __half* __restrict__ Wt,
    const float* __restrict__ bias,
    float* __restrict__ C)
{
    extern __shared__ char smem_raw[];
    const uint32_t sbase = smem_to_u32(smem_raw);

    const int tid = threadIdx.x;
    const int wid = tid >> 5;
    const int lane = tid & 31;
    const int m0 = blockIdx.y * BM;
    const int n0 = blockIdx.x * BN;

    const int wm = (wid >> 1) * 64;
    const int wn = (wid & 1) * 64;

    const int lr = tid >> 2;
    const int lc = tid & 3;
    const __half* gA[4];
    const __half* gB[4];
    #pragma unroll
    for (int j = 0; j < 4; ++j) {
        gA[j] = A2 + (size_t)(m0 + lr + 32 * j) * HD + lc * 8;
        gB[j] = Wt + (size_t)(n0 + lr + 32 * j) * HD + lc * 8;
    }
    const uint32_t sA_off = lr * ROWB + lc * 16;
    const uint32_t sB_off = A_STG + lr * ROWB + lc * 16;
    const uint32_t RSTEP32 = 32 * ROWB;

    const int lrow = lane & 15;
    const int lkof = (lane >> 4) * 16;
    const uint32_t aAddrBase = sbase + (wm + lrow) * ROWB + lkof;
    const uint32_t bAddrBase = sbase + A_STG + (wn + lrow) * ROWB + lkof;

    float acc[4][8][4];
    #pragma unroll
    for (int i = 0; i < 4; ++i)
        #pragma unroll
        for (int j = 0; j < 8; ++j)
            #pragma unroll
            for (int q = 0; q < 4; ++q) acc[i][j][q] = 0.0f;

    #pragma unroll
    for (int p = 0; p < 4; ++p) {
        const uint32_t sb = sbase + p * STG;
        const size_t go = (size_t)p * BK;
        #pragma unroll
        for (int j = 0; j < 4; ++j) {
            cp_async16(sb + sA_off + j * RSTEP32, gA[j] + go);
            cp_async16(sb + sB_off + j * RSTEP32, gB[j] + go);
        }
        CP_COMMIT();
    }

    int s_c = 0;
    int s_q = 4;
    #pragma unroll 1
    for (int kc = 0; kc < NCHK; ++kc) {
        CP_WAIT3();
        __syncthreads();

        const int q = kc + 4;
        if (q < NCHK) {
            const uint32_t sb = sbase + s_q * STG;
            const size_t go = (size_t)q * BK;
            #pragma unroll
            for (int j = 0; j < 4; ++j) {
                cp_async16(sb + sA_off + j * RSTEP32, gA[j] + go);
                cp_async16(sb + sB_off + j * RSTEP32, gB[j] + go);
            }
        }
        CP_COMMIT();

        const uint32_t stg = s_c * STG;
        uint32_t a0[4][4], b0[4][4], a1[4][4], b1[4][4];
        #pragma unroll
        for (int i = 0; i < 4; ++i)
            ldsm_x4(a0[i], aAddrBase + stg + i * (16 * ROWB));
        #pragma unroll
        for (int j = 0; j < 4; ++j)
            ldsm_x4(b0[j], bAddrBase + stg + j * (16 * ROWB));
        #pragma unroll
        for (int i = 0; i < 4; ++i)
            ldsm_x4(a1[i], aAddrBase + stg + 32 + i * (16 * ROWB));
        #pragma unroll
        for (int j = 0; j < 4; ++j)
            ldsm_x4(b1[j], bAddrBase + stg + 32 + j * (16 * ROWB));

        #pragma unroll
        for (int i = 0; i < 4; ++i) {
            #pragma unroll
            for (int j = 0; j < 4; ++j) {
                mma16816(acc[i][2 * j + 0], a0[i], b0[j][0], b0[j][2]);
                mma16816(acc[i][2 * j + 1], a0[i], b0[j][1], b0[j][3]);
            }
        }
        #pragma unroll
        for (int i = 0; i < 4; ++i) {
            #pragma unroll
            for (int j = 0; j < 4; ++j) {
                mma16816(acc[i][2 * j + 0], a1[i], b1[j][0], b1[j][2]);
                mma16816(acc[i][2 * j + 1], a1[i], b1[j][1], b1[j][3]);
            }
        }

        if (++s_c == NSTAGE) s_c = 0;
        if (++s_q == NSTAGE) s_q = 0;
    }

    const int g = lane >> 2;
    const int t = lane & 3;
    #pragma unroll
    for (int i = 0; i < 4; ++i) {
        const int row = m0 + wm + i * 16 + g;
        #pragma unroll
        for (int j = 0; j < 8; ++j) {
            const int col = n0 + wn + j * 8 + t * 2;
            const float b0 = bias[col], b1 = bias[col + 1];
            float2 v0 = make_float2(acc[i][j][0] + b0, acc[i][j][1] + b1);
            float2 v1 = make_float2(acc[i][j][2] + b0, acc[i][j][3] + b1);
            *(float2*)(C + (size_t)row * HD + col) = v0;
            *(float2*)(C + (size_t)(row + 8) * HD + col) = v1;
        }
    }
}

// ---------------------------------------------------------------------------
// LN1 + hierarchical fusion (one block per row; emb via __ldg, fused reductions)
// Writes fp16 F for multiscale.
// ---------------------------------------------------------------------------
__global__ __launch_bounds__(256) void ln1_fusion_kernel(
    const float* __restrict__ Y, const float* __restrict__ masks,
    const float* __restrict__ emb,
    const float* __restrict__ g, const float* __restrict__ bvec,
    __half* __restrict__ Fout)
{
    __shared__ float sbuf[72];

    const int row = blockIdx.x;
    const int c = threadIdx.x * 4;

    const float4 y = *(const float4*)(Y + (size_t)row * HD + c);
    float sum, sumsq;
    blk_reduce2(y.x + y.y + y.z + y.w,
                y.x * y.x + y.y * y.y + y.z * y.z + y.w * y.w,
                sbuf, sum, sumsq);
    const float mu   = sum * (1.0f / HD);
    const float var  = sumsq * (1.0f / HD) - mu * mu;
    const float rstd = rsqrtf(var + 1e-5f);

    const float4 gv = __ldg((const float4*)(g + c));
    const float4 bv = __ldg((const float4*)(bvec + c));
    const float t0 = (y.x - mu) * rstd * gv.x + bv.x;
    const float t1 = (y.y - mu) * rstd * gv.y + bv.y;
    const float t2 = (y.z - mu) * rstd * gv.z + bv.z;
    const float t3 = (y.w - mu) * rstd * gv.w + bv.w;

    // embeddings for these 4 columns (L1-cached, reused for f below)
    const float4 e0 = __ldg((const float4*)(emb + 0 * HD + c));
    const float4 e1 = __ldg((const float4*)(emb + 1 * HD + c));
    const float4 e2 = __ldg((const float4*)(emb + 2 * HD + c));
    const float4 e3 = __ldg((const float4*)(emb + 3 * HD + c));

    float sc0, sc1, sc2, sc3;
    blk_reduce4(t0 * e0.x + t1 * e0.y + t2 * e0.z + t3 * e0.w,
                t0 * e1.x + t1 * e1.y + t2 * e1.z + t3 * e1.w,
                t0 * e2.x + t1 * e2.y + t2 * e2.z + t3 * e2.w,
                t0 * e3.x + t1 * e3.y + t2 * e3.z + t3 * e3.w,
                sbuf, sc0, sc1, sc2, sc3);

    const float4 mk = __ldg((const float4*)(masks + (size_t)row * 4));
    const float wn0 = (mk.x > 0.5f) ? expf(sc0) : 0.0f;
    const float wn1 = (mk.y > 0.5f) ? expf(sc1) : 0.0f;
    const float wn2 = (mk.z > 0.5f) ? expf(sc2) : 0.0f;
    const float wn3 = (mk.w > 0.5f) ? expf(sc3) : 0.0f;
    const float tot = wn0 + wn1 + wn2 + wn3;
    const float inv = (tot > 1e-8f) ? (1.0f / tot) : 1.0f;
    const float q0 = wn0 * inv, q1 = wn1 * inv, q2 = wn2 * inv, q3 = wn3 * inv;

    // fused vector for these 4 columns (note: e-vectors are per-level rows;
    // component i of f uses e{n}.component_i)
    const float f0 = q0 * e0.x + q1 * e1.x + q2 * e2.x + q3 * e3.x;
    const float f1 = q0 * e0.y + q1 * e1.y + q2 * e2.y + q3 * e3.y;
    const float f2 = q0 * e0.z + q1 * e1.z + q2 * e2.z + q3 * e3.z;
    const float f3 = q0 * e0.w + q1 * e1.w + q2 * e2.w + q3 * e3.w;

    const float gsum = blk_reduce1(f0 * t0 + f1 * t1 + f2 * t2 + f3 * t3, sbuf);
    const float gate = 1.0f / (1.0f + expf(-gsum * (1.0f / HD)));
    const float og = 1.0f - gate;

    const __half2 h01 = __floats2half2_rn(gate * f0 + og * t0, gate * f1 + og * t1);
    const __half2 h23 = __floats2half2_rn(gate * f2 + og * t2, gate * f3 + og * t3);
    __half2 hv[2] = {h01, h23};
    *(uint2*)(Fout + (size_t)row * HD + c) = *(uint2*)hv;
}

// wait: score uses dot(t, emb[n]) = sum over columns of t[c]*emb[n][c].
// e{n}.x..w above are emb[n][c..c+3] -> partial = t0*en.x + t1*en.y + ... OK.

// ---------------------------------------------------------------------------
// Multi-scale windowed means along L (scales 1,3,7,15), fp16 in / fp16 out
// ---------------------------------------------------------------------------
__global__ __launch_bounds__(256) void multiscale_kernel(
    const __half* __restrict__ F, __half* __restrict__ A2)
{
    const int L = LSEQ, H = HD;
    const int SL = 128;

    const int gtid = blockIdx.x * 256 + threadIdx.x;
    const int h = gtid & (H - 1);
    const int rest = gtid >> 10;
    const int b = rest & 7;
    const int strip = rest >> 3;
    const int s0 = strip * SL;

    const __half* base = F + (size_t)b * L * H + h;
    __half* oA = A2 + (size_t)b * L * H + h;

    const float SW3  = (float)(1.0 / (1.0 + 1.0986122886681098));
    const float SW7  = (float)(1.0 / (1.0 + 1.9459101090932196));
    const float SW15 = (float)(1.0 / (1.0 + 2.7080502011022101));

    if (strip > 0 && strip < 31) {
        float ring[16];
        #pragma unroll
        for (int j = -8; j <= 6; ++j)
            ring[j & 15] = __half2float(base[(size_t)(s0 + j) * H]);

        float s3 = 0.f, s7 = 0.f, s15 = 0.f;
        #pragma unroll
        for (int j = -8; j <= 6; ++j) {
            const float v = ring[j & 15];
            const int d = j + 1;
            if (d >= -7 && d <= 7) s15 += v;
            if (d >= -3 && d <= 3) s7  += v;
            if (d >= -1 && d <= 1) s3  += v;
        }

        const float w3 = SW3 * (1.0f / 3.0f);
        const float w7 = SW7 * (1.0f / 7.0f);
        const float w15 = SW15 * (1.0f / 15.0f);

        #pragma unroll 1
        for (int cch = 0; cch < SL; cch += 16) {
            #pragma unroll
            for (int i = 0; i < 16; ++i) {
                const int l = s0 + cch + i;
                const float nv = __half2float(base[(size_t)(l + 7) * H]);
                ring[(i + 7) & 15] = nv;
                s3  += ring[(i + 1) & 15] - ring[(i - 2) & 15];
                s7  += ring[(i + 3) & 15] - ring[(i - 4) & 15];
                s15 += nv               - ring[(i - 8) & 15];
                const float s1 = ring[i & 15];
                oA[(size_t)l * H] = __float2half_rn(s1 + s3 * w3 + s7 * w7 + s15 * w15);
            }
        }
    } else {
        for (int l = s0; l < s0 + SL; ++l) {
            float s3 = 0.f, s7 = 0.f, s15 = 0.f;
            #pragma unroll
            for (int j = -7; j <= 7; ++j) {
                const int p = l + j;
                const float v = (p >= 0 && p < L)
                    ? __half2float(base[(size_t)p * H]) : 0.0f;
                s15 += v;
                if (j >= -3 && j <= 3) s7 += v;
                if (j >= -1 && j <= 1) s3 += v;
            }
            const float s1 = __half2float(base[(size_t)l * H]);
            const int cnt3  = min(l + 2, L) - max(l - 1, 0);
            const int cnt7  = min(l + 4, L) - max(l - 3, 0);
            const int cnt15 = min(l + 8, L) - max(l - 7, 0);
            const float outv = s1
                + SW3  * s3  / (float)cnt3
                + SW7  * s7  / (float)cnt7
                + SW15 * s15 / (float)cnt15;
            oA[(size_t)l * H] = __float2half_rn(outv);
        }
    }
}

// ---------------------------------------------------------------------------
// LN2 + residual (one block per row, fused dual reduction)
// ---------------------------------------------------------------------------
__global__ __launch_bounds__(256) void ln2_res_kernel(
    const float* __restrict__ Y, const float* __restrict__ X,
    const float* __restrict__ g, const float* __restrict__ bvec,
    float* __restrict__ out)
{
    __shared__ float sbuf[72];
    const int row = blockIdx.x;
    const int c = threadIdx.x * 4;

    const float4 y = *(const float4*)(Y + (size_t)row * HD + c);
    float sum, sumsq;
    blk_reduce2(y.x + y.y + y.z + y.w,
                y.x * y.x + y.y * y.y + y.z * y.z + y.w * y.w,
                sbuf, sum, sumsq);
    const float mu   = sum * (1.0f / HD);
    const float var  = sumsq * (1.0f / HD) - mu * mu;
    const float rstd = rsqrtf(var + 1e-5f);

    const float4 gv = __ldg((const float4*)(g + c));
    const float4 bv = __ldg((const float4*)(bvec + c));
    const float4 xv = *(const float4*)(X + (size_t)row * HD + c);

    float4 o;
    o.x = (y.x - mu) * rstd * gv.x + bv.x + xv.x;
    o.y = (y.y - mu) * rstd * gv.y + bv.y + xv.y;
    o.z = (y.z - mu) * rstd * gv.z + bv.z + xv.z;
    o.w = (y.w - mu) * rstd * gv.w + bv.w + xv.w;
    *(float4*)(out + (size_t)row * HD + c) = o;
}

// ---------------------------------------------------------------------------
// Launcher
// ---------------------------------------------------------------------------
extern "C" void kernel_launch(void* const* d_in, const int* in_sizes, int n_in,
                              void* d_out, int out_size)
{
    const float* X   = (const float*)d_in[0];
    const float* msk = (const float*)d_in[1];
    const float* emb = (const float*)d_in[2];
    const float* ltw = (const float*)d_in[3];
    const float* ltb = (const float*)d_in[4];
    const float* g1  = (const float*)d_in[5];
    const float* b1  = (const float*)d_in[6];
    const float* ftw = (const float*)d_in[7];
    const float* ftb = (const float*)d_in[8];
    const float* g2  = (const float*)d_in[9];
    const float* b2  = (const float*)d_in[10];
    float* out = (float*)d_out;

    float *bufA, *bufB;
    __half *A2, *Wt1, *Wt2;
    cudaGetSymbolAddress((void**)&bufA, g_bufA);
    cudaGetSymbolAddress((void**)&bufB, g_bufB);
    cudaGetSymbolAddress((void**)&A2,  g_A2);
    cudaGetSymbolAddress((void**)&Wt1, g_Wt1);
    cudaGetSymbolAddress((void**)&Wt2, g_Wt2);
    __half* Fh = (__half*)bufB;    // fp16 F lives in bufB's storage

    cudaFuncSetAttribute((const void*)gemm_mma_kernel,
                         cudaFuncAttributeMaxDynamicSharedMemorySize, GEMM_SMEM);

    const dim3 ggrid(HD / BN, MROWS / BM);   // (8, 256) = 2048 CTAs

    // weight transposes to fp16 (every call; deterministic)
    convW_kernel<<<(HD * HD) / 256, 256>>>(ltw, Wt1);
    convW_kernel<<<(HD * HD) / 256, 256>>>(ftw, Wt2);

    // 1) Y1 = X @ lt_w + lt_b
    convA_kernel<<<(MROWS * HD / 4) / 256, 256>>>(X, A2);
    gemm_mma_kernel<<<ggrid, 128, GEMM_SMEM>>>(A2, Wt1, ltb, bufA);
    // 2) F = fusion(LN1(Y1)) -> fp16
    ln1_fusion_kernel<<<MROWS, 256>>>(bufA, msk, emb, g1, b1, Fh);
    // 3) agg = multiscale(F), fp16 in/out -> A2
    multiscale_kernel<<<(BDIM * HD * 32) / 256, 256>>>(Fh, A2);
    // 4) Y2 = agg @ ft_w + ft_b
    gemm_mma_kernel<<<ggrid, 128, GEMM_SMEM>>>(A2, Wt2, ftb, bufA);
    // 5) out = LN2(Y2) + X
    ln2_res_kernel<<<MROWS, 256>>>(bufA, X, g2, b2, out);
}

// round 10
// speedup vs baseline: 1.4552x; 1.0165x over previous
#include <cuda_runtime.h>
#include <cuda_fp16.h>
#include <math.h>
#include <stdint.h>

// Problem shape (fixed by setup_inputs)
#define MROWS 32768          // B*L
#define BDIM  8
#define LSEQ  4096
#define HD    1024
#define NL    4
#define NCHK  32             // HD / BK

// GEMM tiling: CTA 128x128, 4 warps (2x2), warp tile 64x64, BK=32
#define BM 128
#define BN 128
#define BK 32
#define NSTAGE 3
#define ROWB 80                           // (32+8) fp16 = 80 bytes per row
#define A_STG (BM * ROWB)                 // 10240
#define B_STG (BN * ROWB)                 // 10240
#define STG   (A_STG + B_STG)             // 20480
#define GEMM_SMEM (NSTAGE * STG)          // 61440 (x3 CTAs = 184KB <= 228KB)

// ---------------------------------------------------------------------------
// Scratch (device globals: allocation-free)
// ---------------------------------------------------------------------------
__device__ float g_bufA[(size_t)MROWS * HD];
__device__ float g_bufB[(size_t)MROWS * HD];     // reused as fp16 F / fp16 Y2
__device__ __align__(256) __half g_A2[(size_t)MROWS * HD];    // fp16 A
__device__ __align__(256) __half g_Wt1[(size_t)HD * HD];      // lt_w^T fp16
__device__ __align__(256) __half g_Wt2[(size_t)HD * HD];      // ft_w^T fp16

// ---------------------------------------------------------------------------
// PTX helpers (sm_80-class features only: cp.async, ldmatrix, mma.sync)
// ---------------------------------------------------------------------------
__device__ __forceinline__ uint32_t smem_to_u32(const void* p) {
    uint32_t a;
    asm("{ .reg .u64 t; cvta.to.shared.u64 t, %1; cvt.u32.u64 %0, t; }" : "=r"(a) : "l"(p));
    return a;
}
__device__ __forceinline__ void cp_async16(uint32_t dst, const void* src) {
    asm volatile("cp.async.cg.shared.global [%0], [%1], 16;\n" :: "r"(dst), "l"(src) : "memory");
}
#define CP_COMMIT() asm volatile("cp.async.commit_group;" ::: "memory")
#define CP_WAIT1()  asm volatile("cp.async.wait_group 1;" ::: "memory")

__device__ __forceinline__ void ldsm_x4(uint32_t (&r)[4], uint32_t addr) {
    asm volatile("ldmatrix.sync.aligned.m8n8.x4.shared.b16 {%0,%1,%2,%3}, [%4];"
        : "=r"(r[0]), "=r"(r[1]), "=r"(r[2]), "=r"(r[3]) : "r"(addr));
}
__device__ __forceinline__ void mma16816(float (&c)[4],
                                         const uint32_t (&a)[4],
                                         uint32_t b0, uint32_t b1) {
    asm volatile(
        "mma.sync.aligned.m16n8k16.row.col.f32.f16.f16.f32 "
        "{%0,%1,%2,%3}, {%4,%5,%6,%7}, {%8,%9}, {%0,%1,%2,%3};"
        : "+f"(c[0]), "+f"(c[1]), "+f"(c[2]), "+f"(c[3])
        : "r"(a[0]), "r"(a[1]), "r"(a[2]), "r"(a[3]), "r"(b0), "r"(b1));
}

__device__ __forceinline__ float warp_sum(float v) {
    #pragma unroll
    for (int o = 16; o > 0; o >>= 1) v += __shfl_xor_sync(0xffffffffu, v, o);
    return v;
}

// ---- fused block reductions (256 threads, 8 warps), disjoint sbuf regions ----
__device__ __forceinline__ void blk_reduce2(float v1, float v2, float* sbuf,
                                            float& r1, float& r2)
{
    v1 = warp_sum(v1); v2 = warp_sum(v2);
    const int lane = threadIdx.x & 31, w = threadIdx.x >> 5;
    if (lane == 0) { sbuf[w] = v1; sbuf[8 + w] = v2; }
    __syncthreads();
    if (threadIdx.x < 16) {
        float x = sbuf[threadIdx.x];
        x += __shfl_xor_sync(0xffffu, x, 4);
        x += __shfl_xor_sync(0xffffu, x, 2);
        x += __shfl_xor_sync(0xffffu, x, 1);
        if ((threadIdx.x & 7) == 0) sbuf[16 + (threadIdx.x >> 3)] = x;
    }
    __syncthreads();
    r1 = sbuf[16]; r2 = sbuf[17];
}

__device__ __forceinline__ void blk_reduce4(float p0, float p1, float p2, float p3,
                                            float* sbuf,
                                            float& r0, float& r1, float& r2, float& r3)
{
    p0 = warp_sum(p0); p1 = warp_sum(p1); p2 = warp_sum(p2); p3 = warp_sum(p3);
    const int lane = threadIdx.x & 31, w = threadIdx.x >> 5;
    if (lane == 0) {
        sbuf[20 + w] = p0; sbuf[28 + w] = p1; sbuf[36 + w] = p2; sbuf[44 + w] = p3;
    }
    __syncthreads();
    if (threadIdx.x < 32) {
        float x = sbuf[20 + threadIdx.x];
        x += __shfl_xor_sync(0xffffffffu, x, 4);
        x += __shfl_xor_sync(0xffffffffu, x, 2);
        x += __shfl_xor_sync(0xffffffffu, x, 1);
        if ((threadIdx.x & 7) == 0) sbuf[52 + (threadIdx.x >> 3)] = x;
    }
    __syncthreads();
    r0 = sbuf[52]; r1 = sbuf[53]; r2 = sbuf[54]; r3 = sbuf[55];
}

__device__ __forceinline__ float blk_reduce1(float v, float* sbuf)
{
    v = warp_sum(v);
    const int lane = threadIdx.x & 31, w = threadIdx.x >> 5;
    if (lane == 0) sbuf[56 + w] = v;
    __syncthreads();
    if (threadIdx.x < 8) {
        float x = sbuf[56 + threadIdx.x];
        x += __shfl_xor_sync(0xffu, x, 4);
        x += __shfl_xor_sync(0xffu, x, 2);
        x += __shfl_xor_sync(0xffu, x, 1);
        if (threadIdx.x == 0) sbuf[64] = x;
    }
    __syncthreads();
    return sbuf[64];
}

// ---------------------------------------------------------------------------
// fp32 -> fp16 conversion of A [M, HD]
// ---------------------------------------------------------------------------
__global__ __launch_bounds__(256) void convA_kernel(
    const float* __restrict__ A, __half* __restrict__ A2)
{
    const size_t i = (size_t)blockIdx.x * 256 + threadIdx.x;
    const float4 v = *(const float4*)(A + i * 4);
    __half h[4];
    h[0] = __float2half_rn(v.x); h[1] = __float2half_rn(v.y);
    h[2] = __float2half_rn(v.z); h[3] = __float2half_rn(v.w);
    ((unsigned long long*)A2)[i] = *(const unsigned long long*)h;
}

// W[HD,HD] fp32 -> Wt[n][k] fp16 (transposed)
__global__ __launch_bounds__(256) void convW_kernel(
    const float* __restrict__ W, __half* __restrict__ Wt)
{
    const int idx = blockIdx.x * 256 + threadIdx.x;   // HD*HD threads
    const int n = idx & (HD - 1);
    const int k = idx >> 10;
    Wt[(size_t)n * HD + k] = __float2half_rn(W[(size_t)k * HD + n]);
}

// ---------------------------------------------------------------------------
// mma.sync GEMM: CTA 128x128, 4 warps (2x2), warp tile 64x64, BK=32,
// 3-stage cp.async, 3 CTAs/SM (regs capped at 170 via launch_bounds).
// Sequential ks-half processing keeps live fragments at 32 regs.
// Templated output type: fp32 (GEMM1) or fp16 (GEMM2, feeds ln2).
// ---------------------------------------------------------------------------
template <typename OutT>
__global__ __launch_bounds__(128, 3) void gemm_mma_kernel(
    const __half* __restrict__ A2,
    const __half* __restrict__ Wt,
    const float* __restrict__ bias,
    OutT* __restrict__ C)
{
    extern __shared__ char smem_raw[];
    const uint32_t sbase = smem_to_u32(smem_raw);

    const int tid = threadIdx.x;
    const int wid = tid >> 5;
    const int lane = tid & 31;
    const int m0 = blockIdx.y * BM;
    const int n0 = blockIdx.x * BN;

    const int wm = (wid >> 1) * 64;
    const int wn = (wid & 1) * 64;

    const int lr = tid >> 2;
    const int lc = tid & 3;
    const __half* gA[4];
    const __half* gB[4];
    #pragma unroll
    for (int j = 0; j < 4; ++j) {
        gA[j] = A2 + (size_t)(m0 + lr + 32 * j) * HD + lc * 8;
        gB[j] = Wt + (size_t)(n0 + lr + 32 * j) * HD + lc * 8;
    }
    const uint32_t sA_off = lr * ROWB + lc * 16;
    const uint32_t sB_off = A_STG + lr * ROWB + lc * 16;
    const uint32_t RSTEP32 = 32 * ROWB;

    const int lrow = lane & 15;
    const int lkof = (lane >> 4) * 16;
    const uint32_t aAddrBase = sbase + (wm + lrow) * ROWB + lkof;
    const uint32_t bAddrBase = sbase + A_STG + (wn + lrow) * ROWB + lkof;

    float acc[4][8][4];
    #pragma unroll
    for (int i = 0; i < 4; ++i)
        #pragma unroll
        for (int j = 0; j < 8; ++j)
            #pragma unroll
            for (int q = 0; q < 4; ++q) acc[i][j][q] = 0.0f;

    // prologue: chunks 0,1 into stages 0,1
    #pragma unroll
    for (int p = 0; p < 2; ++p) {
        const uint32_t sb = sbase + p * STG;
        const size_t go = (size_t)p * BK;
        #pragma unroll
        for (int j = 0; j < 4; ++j) {
            cp_async16(sb + sA_off + j * RSTEP32, gA[j] + go);
            cp_async16(sb + sB_off + j * RSTEP32, gB[j] + go);
        }
        CP_COMMIT();
    }

    int s_c = 0;   // stage of chunk kc
    int s_q = 2;   // stage of chunk kc+2
    #pragma unroll 1
    for (int kc = 0; kc < NCHK; ++kc) {
        CP_WAIT1();               // chunk kc landed (<=1 younger outstanding)
        __syncthreads();

        // issue loads for chunk kc+2 (stage held chunk kc-1, done by all warps)
        const int q = kc + 2;
        if (q < NCHK) {
            const uint32_t sb = sbase + s_q * STG;
            const size_t go = (size_t)q * BK;
            #pragma unroll
            for (int j = 0; j < 4; ++j) {
                cp_async16(sb + sA_off + j * RSTEP32, gA[j] + go);
                cp_async16(sb + sB_off + j * RSTEP32, gB[j] + go);
            }
        }
        CP_COMMIT();

        const uint32_t stg = s_c * STG;
        #pragma unroll
        for (int ks = 0; ks < 2; ++ks) {
            uint32_t a[4][4], b[4][4];
            const uint32_t kb = stg + ks * 32;
            #pragma unroll
            for (int i = 0; i < 4; ++i)
                ldsm_x4(a[i], aAddrBase + kb + i * (16 * ROWB));
            #pragma unroll
            for (int j = 0; j < 4; ++j)
                ldsm_x4(b[j], bAddrBase + kb + j * (16 * ROWB));
            #pragma unroll
            for (int i = 0; i < 4; ++i) {
                #pragma unroll
                for (int j = 0; j < 4; ++j) {
                    mma16816(acc[i][2 * j + 0], a[i], b[j][0], b[j][2]);
                    mma16816(acc[i][2 * j + 1], a[i], b[j][1], b[j][3]);
                }
            }
        }

        if (++s_c == NSTAGE) s_c = 0;
        if (++s_q == NSTAGE) s_q = 0;
    }

    // epilogue: bias add + store (fp32 or fp16 per OutT)
    const int g = lane >> 2;
    const int t = lane & 3;
    #pragma unroll
    for (int i = 0; i < 4; ++i) {
        const int row = m0 + wm + i * 16 + g;
        #pragma unroll
        for (int j = 0; j < 8; ++j) {
            const int col = n0 + wn + j * 8 + t * 2;
            const float b0 = bias[col], b1 = bias[col + 1];
            const float v00 = acc[i][j][0] + b0, v01 = acc[i][j][1] + b1;
            const float v10 = acc[i][j][2] + b0, v11 = acc[i][j][3] + b1;
            if (sizeof(OutT) == 4) {
                *(float2*)((float*)C + (size_t)row * HD + col) = make_float2(v00, v01);
                *(float2*)((float*)C + (size_t)(row + 8) * HD + col) = make_float2(v10, v11);
            } else {
                *(__half2*)((__half*)C + (size_t)row * HD + col) = __floats2half2_rn(v00, v01);
                *(__half2*)((__half*)C + (size_t)(row + 8) * HD + col) = __floats2half2_rn(v10, v11);
            }
        }
    }
}

// ---------------------------------------------------------------------------
// LN1 + hierarchical fusion (one block per row; emb via __ldg, fused reductions)
// Writes fp16 F for multiscale.
// ---------------------------------------------------------------------------
__global__ __launch_bounds__(256) void ln1_fusion_kernel(
    const float* __restrict__ Y, const float* __restrict__ masks,
    const float* __restrict__ emb,
    const float* __restrict__ g, const float* __restrict__ bvec,
    __half* __restrict__ Fout)
{
    __shared__ float sbuf[72];

    const int row = blockIdx.x;
    const int c = threadIdx.x * 4;

    const float4 y = *(const float4*)(Y + (size_t)row * HD + c);
    float sum, sumsq;
    blk_reduce2(y.x + y.y + y.z + y.w,
                y.x * y.x + y.y * y.y + y.z * y.z + y.w * y.w,
                sbuf, sum, sumsq);
    const float mu   = sum * (1.0f / HD);
    const float var  = sumsq * (1.0f / HD) - mu * mu;
    const float rstd = rsqrtf(var + 1e-5f);

    const float4 gv = __ldg((const float4*)(g + c));
    const float4 bv = __ldg((const float4*)(bvec + c));
    const float t0 = (y.x - mu) * rstd * gv.x + bv.x;
    const float t1 = (y.y - mu) * rstd * gv.y + bv.y;
    const float t2 = (y.z - mu) * rstd * gv.z + bv.z;
    const float t3 = (y.w - mu) * rstd * gv.w + bv.w;

    const float4 e0 = __ldg((const float4*)(emb + 0 * HD + c));
    const float4 e1 = __ldg((const float4*)(emb + 1 * HD + c));
    const float4 e2 = __ldg((const float4*)(emb + 2 * HD + c));
    const float4 e3 = __ldg((const float4*)(emb + 3 * HD + c));

    float sc0, sc1, sc2, sc3;
    blk_reduce4(t0 * e0.x + t1 * e0.y + t2 * e0.z + t3 * e0.w,
                t0 * e1.x + t1 * e1.y + t2 * e1.z + t3 * e1.w,
                t0 * e2.x + t1 * e2.y + t2 * e2.z + t3 * e2.w,
                t0 * e3.x + t1 * e3.y + t2 * e3.z + t3 * e3.w,
                sbuf, sc0, sc1, sc2, sc3);

    const float4 mk = __ldg((const float4*)(masks + (size_t)row * 4));
    const float wn0 = (mk.x > 0.5f) ? expf(sc0) : 0.0f;
    const float wn1 = (mk.y > 0.5f) ? expf(sc1) : 0.0f;
    const float wn2 = (mk.z > 0.5f) ? expf(sc2) : 0.0f;
    const float wn3 = (mk.w > 0.5f) ? expf(sc3) : 0.0f;
    const float tot = wn0 + wn1 + wn2 + wn3;
    const float inv = (tot > 1e-8f) ? (1.0f / tot) : 1.0f;
    const float q0 = wn0 * inv, q1 = wn1 * inv, q2 = wn2 * inv, q3 = wn3 * inv;

    const float f0 = q0 * e0.x + q1 * e1.x + q2 * e2.x + q3 * e3.x;
    const float f1 = q0 * e0.y + q1 * e1.y + q2 * e2.y + q3 * e3.y;
    const float f2 = q0 * e0.z + q1 * e1.z + q2 * e2.z + q3 * e3.z;
    const float f3 = q0 * e0.w + q1 * e1.w + q2 * e2.w + q3 * e3.w;

    const float gsum = blk_reduce1(f0 * t0 + f1 * t1 + f2 * t2 + f3 * t3, sbuf);
    const float gate = 1.0f / (1.0f + expf(-gsum * (1.0f / HD)));
    const float og = 1.0f - gate;

    const __half2 h01 = __floats2half2_rn(gate * f0 + og * t0, gate * f1 + og * t1);
    const __half2 h23 = __floats2half2_rn(gate * f2 + og * t2, gate * f3 + og * t3);
    __half2 hv[2] = {h01, h23};
    *(uint2*)(Fout + (size_t)row * HD + c) = *(uint2*)hv;
}

// ---------------------------------------------------------------------------
// Multi-scale windowed means along L (scales 1,3,7,15), fp16 in / fp16 out
// ---------------------------------------------------------------------------
__global__ __launch_bounds__(256) void multiscale_kernel(
    const __half* __restrict__ F, __half* __restrict__ A2)
{
    const int L = LSEQ, H = HD;
    const int SL = 128;

    const int gtid = blockIdx.x * 256 + threadIdx.x;
    const int h = gtid & (H - 1);
    const int rest = gtid >> 10;
    const int b = rest & 7;
    const int strip = rest >> 3;
    const int s0 = strip * SL;

    const __half* base = F + (size_t)b * L * H + h;
    __half* oA = A2 + (size_t)b * L * H + h;

    const float SW3  = (float)(1.0 / (1.0 + 1.0986122886681098));
    const float SW7  = (float)(1.0 / (1.0 + 1.9459101090932196));
    const float SW15 = (float)(1.0 / (1.0 + 2.7080502011022101));

    if (strip > 0 && strip < 31) {
        float ring[16];
        #pragma unroll
        for (int j = -8; j <= 6; ++j)
            ring[j & 15] = __half2float(base[(size_t)(s0 + j) * H]);

        float s3 = 0.f, s7 = 0.f, s15 = 0.f;
        #pragma unroll
        for (int j = -8; j <= 6; ++j) {
            const float v = ring[j & 15];
            const int d = j + 1;
            if (d >= -7 && d <= 7) s15 += v;
            if (d >= -3 && d <= 3) s7  += v;
            if (d >= -1 && d <= 1) s3  += v;
        }

        const float w3 = SW3 * (1.0f / 3.0f);
        const float w7 = SW7 * (1.0f / 7.0f);
        const float w15 = SW15 * (1.0f / 15.0f);

        #pragma unroll 1
        for (int cch = 0; cch < SL; cch += 16) {
            #pragma unroll
            for (int i = 0; i < 16; ++i) {
                const int l = s0 + cch + i;
                const float nv = __half2float(base[(size_t)(l + 7) * H]);
                ring[(i + 7) & 15] = nv;
                s3  += ring[(i + 1) & 15] - ring[(i - 2) & 15];
                s7  += ring[(i + 3) & 15] - ring[(i - 4) & 15];
                s15 += nv               - ring[(i - 8) & 15];
                const float s1 = ring[i & 15];
                oA[(size_t)l * H] = __float2half_rn(s1 + s3 * w3 + s7 * w7 + s15 * w15);
            }
        }
    } else {
        for (int l = s0; l < s0 + SL; ++l) {
            float s3 = 0.f, s7 = 0.f, s15 = 0.f;
            #pragma unroll
            for (int j = -7; j <= 7; ++j) {
                const int p = l + j;
                const float v = (p >= 0 && p < L)
                    ? __half2float(base[(size_t)p * H]) : 0.0f;
                s15 += v;
                if (j >= -3 && j <= 3) s7 += v;
                if (j >= -1 && j <= 1) s3 += v;
            }
            const float s1 = __half2float(base[(size_t)l * H]);
            const int cnt3  = min(l + 2, L) - max(l - 1, 0);
            const int cnt7  = min(l + 4, L) - max(l - 3, 0);
            const int cnt15 = min(l + 8, L) - max(l - 7, 0);
            const float outv = s1
                + SW3  * s3  / (float)cnt3
                + SW7  * s7  / (float)cnt7
                + SW15 * s15 / (float)cnt15;
            oA[(size_t)l * H] = __float2half_rn(outv);
        }
    }
}

// ---------------------------------------------------------------------------
// LN2 + residual (one block per row, fused dual reduction, fp16 Y input)
// ---------------------------------------------------------------------------
__global__ __launch_bounds__(256) void ln2_res_kernel(
    const __half* __restrict__ Y, const float* __restrict__ X,
    const float* __restrict__ g, const float* __restrict__ bvec,
    float* __restrict__ out)
{
    __shared__ float sbuf[72];
    const int row = blockIdx.x;
    const int c = threadIdx.x * 4;

    const uint2 yraw = *(const uint2*)(Y + (size_t)row * HD + c);
    const __half2 yh0 = *(const __half2*)&yraw.x;
    const __half2 yh1 = *(const __half2*)&yraw.y;
    const float2 ya = __half22float2(yh0);
    const float2 yb = __half22float2(yh1);
    const float y0 = ya.x, y1 = ya.y, y2 = yb.x, y3 = yb.y;

    float sum, sumsq;
    blk_reduce2(y0 + y1 + y2 + y3,
                y0 * y0 + y1 * y1 + y2 * y2 + y3 * y3,
                sbuf, sum, sumsq);
    const float mu   = sum * (1.0f / HD);
    const float var  = sumsq * (1.0f / HD) - mu * mu;
    const float rstd = rsqrtf(var + 1e-5f);

    const float4 gv = __ldg((const float4*)(g + c));
    const float4 bv = __ldg((const float4*)(bvec + c));
    const float4 xv = *(const float4*)(X + (size_t)row * HD + c);

    float4 o;
    o.x = (y0 - mu) * rstd * gv.x + bv.x + xv.x;
    o.y = (y1 - mu) * rstd * gv.y + bv.y + xv.y;
    o.z = (y2 - mu) * rstd * gv.z + bv.z + xv.z;
    o.w = (y3 - mu) * rstd * gv.w + bv.w + xv.w;
    *(float4*)(out + (size_t)row * HD + c) = o;
}

// ---------------------------------------------------------------------------
// Launcher
// ---------------------------------------------------------------------------
extern "C" void kernel_launch(void* const* d_in, const int* in_sizes, int n_in,
                              void* d_out, int out_size)
{
    const float* X   = (const float*)d_in[0];
    const float* msk = (const float*)d_in[1];
    const float* emb = (const float*)d_in[2];
    const float* ltw = (const float*)d_in[3];
    const float* ltb = (const float*)d_in[4];
    const float* g1  = (const float*)d_in[5];
    const float* b1  = (const float*)d_in[6];
    const float* ftw = (const float*)d_in[7];
    const float* ftb = (const float*)d_in[8];
    const float* g2  = (const float*)d_in[9];
    const float* b2  = (const float*)d_in[10];
    float* out = (float*)d_out;

    float *bufA, *bufB;
    __half *A2, *Wt1, *Wt2;
    cudaGetSymbolAddress((void**)&bufA, g_bufA);
    cudaGetSymbolAddress((void**)&bufB, g_bufB);
    cudaGetSymbolAddress((void**)&A2,  g_A2);
    cudaGetSymbolAddress((void**)&Wt1, g_Wt1);
    cudaGetSymbolAddress((void**)&Wt2, g_Wt2);
    __half* Fh  = (__half*)bufB;              // fp16 F
    __half* Y2h = (__half*)bufB + (size_t)MROWS * HD / 2;  // fp16 Y2 (2nd half)

    cudaFuncSetAttribute((const void*)gemm_mma_kernel<float>,
                         cudaFuncAttributeMaxDynamicSharedMemorySize, GEMM_SMEM);
    cudaFuncSetAttribute((const void*)gemm_mma_kernel<__half>,
                         cudaFuncAttributeMaxDynamicSharedMemorySize, GEMM_SMEM);

    const dim3 ggrid(HD / BN, MROWS / BM);   // (8, 256) = 2048 CTAs

    // weight transposes to fp16 (every call; deterministic)
    convW_kernel<<<(HD * HD) / 256, 256>>>(ltw, Wt1);
    convW_kernel<<<(HD * HD) / 256, 256>>>(ftw, Wt2);

    // 1) Y1 = X @ lt_w + lt_b   (fp32 out)
    convA_kernel<<<(MROWS * HD / 4) / 256, 256>>>(X, A2);
    gemm_mma_kernel<float><<<ggrid, 128, GEMM_SMEM>>>(A2, Wt1, ltb, bufA);
    // 2) F = fusion(LN1(Y1)) -> fp16
    ln1_fusion_kernel<<<MROWS, 256>>>(bufA, msk, emb, g1, b1, Fh);
    // 3) agg = multiscale(F), fp16 in/out -> A2
    multiscale_kernel<<<(BDIM * HD * 32) / 256, 256>>>(Fh, A2);
    // 4) Y2 = agg @ ft_w + ft_b  (fp16 out)
    gemm_mma_kernel<__half><<<ggrid, 128, GEMM_SMEM>>>(A2, Wt2, ftb, Y2h);
    // 5) out = LN2(Y2) + X
    ln2_res_kernel<<<MROWS, 256>>>(Y2h, X, g2, b2, out);
}

// round 11
// speedup vs baseline: 1.4793x; 1.0166x over previous
#include <cuda_runtime.h>
#include <cuda_fp16.h>
#include <math.h>
#include <stdint.h>

// Problem shape (fixed by setup_inputs)
#define MROWS 32768          // B*L
#define BDIM  8
#define LSEQ  4096
#define HD    1024
#define NL    4
#define NCHK  32             // HD / BK

// GEMM tiling: CTA 128x128, 4 warps (2x2), warp tile 64x64, BK=32
#define BM 128
#define BN 128
#define BK 32
#define NSTAGE 3
#define ROWB 80                           // (32+8) fp16 = 80 bytes per row
#define A_STG (BM * ROWB)                 // 10240
#define B_STG (BN * ROWB)                 // 10240
#define STG   (A_STG + B_STG)             // 20480
#define GEMM_SMEM (NSTAGE * STG)          // 61440 (x3 CTAs = 184KB <= 228KB)

// ---------------------------------------------------------------------------
// Scratch (device globals: allocation-free)
// ---------------------------------------------------------------------------
__device__ float g_bufA[(size_t)MROWS * HD];     // low half reused as fp16 Y1
__device__ float g_bufB[(size_t)MROWS * HD];     // fp16 F / fp16 Y2
__device__ __align__(256) __half g_A2[(size_t)MROWS * HD];    // fp16 A
__device__ __align__(256) __half g_Wt1[(size_t)HD * HD];      // lt_w^T fp16
__device__ __align__(256) __half g_Wt2[(size_t)HD * HD];      // ft_w^T fp16

// ---------------------------------------------------------------------------
// PTX helpers (sm_80-class features only: cp.async, ldmatrix, mma.sync)
// ---------------------------------------------------------------------------
__device__ __forceinline__ uint32_t smem_to_u32(const void* p) {
    uint32_t a;
    asm("{ .reg .u64 t; cvta.to.shared.u64 t, %1; cvt.u32.u64 %0, t; }" : "=r"(a) : "l"(p));
    return a;
}
__device__ __forceinline__ void cp_async16(uint32_t dst, const void* src) {
    asm volatile("cp.async.cg.shared.global [%0], [%1], 16;\n" :: "r"(dst), "l"(src) : "memory");
}
#define CP_COMMIT() asm volatile("cp.async.commit_group;" ::: "memory")
#define CP_WAIT1()  asm volatile("cp.async.wait_group 1;" ::: "memory")

__device__ __forceinline__ void ldsm_x4(uint32_t (&r)[4], uint32_t addr) {
    asm volatile("ldmatrix.sync.aligned.m8n8.x4.shared.b16 {%0,%1,%2,%3}, [%4];"
        : "=r"(r[0]), "=r"(r[1]), "=r"(r[2]), "=r"(r[3]) : "r"(addr));
}
__device__ __forceinline__ void mma16816(float (&c)[4],
                                         const uint32_t (&a)[4],
                                         uint32_t b0, uint32_t b1) {
    asm volatile(
        "mma.sync.aligned.m16n8k16.row.col.f32.f16.f16.f32 "
        "{%0,%1,%2,%3}, {%4,%5,%6,%7}, {%8,%9}, {%0,%1,%2,%3};"
        : "+f"(c[0]), "+f"(c[1]), "+f"(c[2]), "+f"(c[3])
        : "r"(a[0]), "r"(a[1]), "r"(a[2]), "r"(a[3]), "r"(b0), "r"(b1));
}

__device__ __forceinline__ float warp_sum(float v) {
    #pragma unroll
    for (int o = 16; o > 0; o >>= 1) v += __shfl_xor_sync(0xffffffffu, v, o);
    return v;
}

// ---- fused block reductions (256 threads, 8 warps), disjoint sbuf regions ----
__device__ __forceinline__ void blk_reduce2(float v1, float v2, float* sbuf,
                                            float& r1, float& r2)
{
    v1 = warp_sum(v1); v2 = warp_sum(v2);
    const int lane = threadIdx.x & 31, w = threadIdx.x >> 5;
    if (lane == 0) { sbuf[w] = v1; sbuf[8 + w] = v2; }
    __syncthreads();
    if (threadIdx.x < 16) {
        float x = sbuf[threadIdx.x];
        x += __shfl_xor_sync(0xffffu, x, 4);
        x += __shfl_xor_sync(0xffffu, x, 2);
        x += __shfl_xor_sync(0xffffu, x, 1);
        if ((threadIdx.x & 7) == 0) sbuf[16 + (threadIdx.x >> 3)] = x;
    }
    __syncthreads();
    r1 = sbuf[16]; r2 = sbuf[17];
}

__device__ __forceinline__ void blk_reduce4(float p0, float p1, float p2, float p3,
                                            float* sbuf,
                                            float& r0, float& r1, float& r2, float& r3)
{
    p0 = warp_sum(p0); p1 = warp_sum(p1); p2 = warp_sum(p2); p3 = warp_sum(p3);
    const int lane = threadIdx.x & 31, w = threadIdx.x >> 5;
    if (lane == 0) {
        sbuf[20 + w] = p0; sbuf[28 + w] = p1; sbuf[36 + w] = p2; sbuf[44 + w] = p3;
    }
    __syncthreads();
    if (threadIdx.x < 32) {
        float x = sbuf[20 + threadIdx.x];
        x += __shfl_xor_sync(0xffffffffu, x, 4);
        x += __shfl_xor_sync(0xffffffffu, x, 2);
        x += __shfl_xor_sync(0xffffffffu, x, 1);
        if ((threadIdx.x & 7) == 0) sbuf[52 + (threadIdx.x >> 3)] = x;
    }
    __syncthreads();
    r0 = sbuf[52]; r1 = sbuf[53]; r2 = sbuf[54]; r3 = sbuf[55];
}

// ---------------------------------------------------------------------------
// fp32 -> fp16 conversion of A [M, HD]
// ---------------------------------------------------------------------------
__global__ __launch_bounds__(256) void convA_kernel(
    const float* __restrict__ A, __half* __restrict__ A2)
{
    const size_t i = (size_t)blockIdx.x * 256 + threadIdx.x;
    const float4 v = *(const float4*)(A + i * 4);
    __half h[4];
    h[0] = __float2half_rn(v.x); h[1] = __float2half_rn(v.y);
    h[2] = __float2half_rn(v.z); h[3] = __float2half_rn(v.w);
    ((unsigned long long*)A2)[i] = *(const unsigned long long*)h;
}

// W[HD,HD] fp32 -> Wt[n][k] fp16 (transposed)
__global__ __launch_bounds__(256) void convW_kernel(
    const float* __restrict__ W, __half* __restrict__ Wt)
{
    const int idx = blockIdx.x * 256 + threadIdx.x;   // HD*HD threads
    const int n = idx & (HD - 1);
    const int k = idx >> 10;
    Wt[(size_t)n * HD + k] = __float2half_rn(W[(size_t)k * HD + n]);
}

// ---------------------------------------------------------------------------
// mma.sync GEMM (UNCHANGED from round 10): CTA 128x128, 4 warps, 64x64 tiles,
// BK=32, 3-stage cp.async, 3 CTAs/SM. Templated output type.
// ---------------------------------------------------------------------------
template <typename OutT>
__global__ __launch_bounds__(128, 3) void gemm_mma_kernel(
    const __half* __restrict__ A2,
    const __half* __restrict__ Wt,
    const float* __restrict__ bias,
    OutT* __restrict__ C)
{
    extern __shared__ char smem_raw[];
    const uint32_t sbase = smem_to_u32(smem_raw);

    const int tid = threadIdx.x;
    const int wid = tid >> 5;
    const int lane = tid & 31;
    const int m0 = blockIdx.y * BM;
    const int n0 = blockIdx.x * BN;

    const int wm = (wid >> 1) * 64;
    const int wn = (wid & 1) * 64;

    const int lr = tid >> 2;
    const int lc = tid & 3;
    const __half* gA[4];
    const __half* gB[4];
    #pragma unroll
    for (int j = 0; j < 4; ++j) {
        gA[j] = A2 + (size_t)(m0 + lr + 32 * j) * HD + lc * 8;
        gB[j] = Wt + (size_t)(n0 + lr + 32 * j) * HD + lc * 8;
    }
    const uint32_t sA_off = lr * ROWB + lc * 16;
    const uint32_t sB_off = A_STG + lr * ROWB + lc * 16;
    const uint32_t RSTEP32 = 32 * ROWB;

    const int lrow = lane & 15;
    const int lkof = (lane >> 4) * 16;
    const uint32_t aAddrBase = sbase + (wm + lrow) * ROWB + lkof;
    const uint32_t bAddrBase = sbase + A_STG + (wn + lrow) * ROWB + lkof;

    float acc[4][8][4];
    #pragma unroll
    for (int i = 0; i < 4; ++i)
        #pragma unroll
        for (int j = 0; j < 8; ++j)
            #pragma unroll
            for (int q = 0; q < 4; ++q) acc[i][j][q] = 0.0f;

    #pragma unroll
    for (int p = 0; p < 2; ++p) {
        const uint32_t sb = sbase + p * STG;
        const size_t go = (size_t)p * BK;
        #pragma unroll
        for (int j = 0; j < 4; ++j) {
            cp_async16(sb + sA_off + j * RSTEP32, gA[j] + go);
            cp_async16(sb + sB_off + j * RSTEP32, gB[j] + go);
        }
        CP_COMMIT();
    }

    int s_c = 0;
    int s_q = 2;
    #pragma unroll 1
    for (int kc = 0; kc < NCHK; ++kc) {
        CP_WAIT1();
        __syncthreads();

        const int q = kc + 2;
        if (q < NCHK) {
            const uint32_t sb = sbase + s_q * STG;
            const size_t go = (size_t)q * BK;
            #pragma unroll
            for (int j = 0; j < 4; ++j) {
                cp_async16(sb + sA_off + j * RSTEP32, gA[j] + go);
                cp_async16(sb + sB_off + j * RSTEP32, gB[j] + go);
            }
        }
        CP_COMMIT();

        const uint32_t stg = s_c * STG;
        #pragma unroll
        for (int ks = 0; ks < 2; ++ks) {
            uint32_t a[4][4], b[4][4];
            const uint32_t kb = stg + ks * 32;
            #pragma unroll
            for (int i = 0; i < 4; ++i)
                ldsm_x4(a[i], aAddrBase + kb + i * (16 * ROWB));
            #pragma unroll
            for (int j = 0; j < 4; ++j)
                ldsm_x4(b[j], bAddrBase + kb + j * (16 * ROWB));
            #pragma unroll
            for (int i = 0; i < 4; ++i) {
                #pragma unroll
                for (int j = 0; j < 4; ++j) {
                    mma16816(acc[i][2 * j + 0], a[i], b[j][0], b[j][2]);
                    mma16816(acc[i][2 * j + 1], a[i], b[j][1], b[j][3]);
                }
            }
        }

        if (++s_c == NSTAGE) s_c = 0;
        if (++s_q == NSTAGE) s_q = 0;
    }

    const int g = lane >> 2;
    const int t = lane & 3;
    #pragma unroll
    for (int i = 0; i < 4; ++i) {
        const int row = m0 + wm + i * 16 + g;
        #pragma unroll
        for (int j = 0; j < 8; ++j) {
            const int col = n0 + wn + j * 8 + t * 2;
            const float b0 = bias[col], b1 = bias[col + 1];
            const float v00 = acc[i][j][0] + b0, v01 = acc[i][j][1] + b1;
            const float v10 = acc[i][j][2] + b0, v11 = acc[i][j][3] + b1;
            if (sizeof(OutT) == 4) {
                *(float2*)((float*)C + (size_t)row * HD + col) = make_float2(v00, v01);
                *(float2*)((float*)C + (size_t)(row + 8) * HD + col) = make_float2(v10, v11);
            } else {
                *(__half2*)((__half*)C + (size_t)row * HD + col) = __floats2half2_rn(v00, v01);
                *(__half2*)((__half*)C + (size_t)(row + 8) * HD + col) = __floats2half2_rn(v10, v11);
            }
        }
    }
}

// ---------------------------------------------------------------------------
// LN1 + hierarchical fusion (one block per row; fp16 Y1 input; gate via
// algebraic identity dot(fused,t) = sum_n q_n * sc_n -> NO third reduction)
// ---------------------------------------------------------------------------
__global__ __launch_bounds__(256) void ln1_fusion_kernel(
    const __half* __restrict__ Y, const float* __restrict__ masks,
    const float* __restrict__ emb,
    const float* __restrict__ g, const float* __restrict__ bvec,
    __half* __restrict__ Fout)
{
    __shared__ float sbuf[56];

    const int row = blockIdx.x;
    const int c = threadIdx.x * 4;

    const uint2 yraw = *(const uint2*)(Y + (size_t)row * HD + c);
    const float2 ya = __half22float2(*(const __half2*)&yraw.x);
    const float2 yb = __half22float2(*(const __half2*)&yraw.y);
    const float y0 = ya.x, y1 = ya.y, y2 = yb.x, y3 = yb.y;

    float sum, sumsq;
    blk_reduce2(y0 + y1 + y2 + y3,
                y0 * y0 + y1 * y1 + y2 * y2 + y3 * y3,
                sbuf, sum, sumsq);
    const float mu   = sum * (1.0f / HD);
    const float var  = sumsq * (1.0f / HD) - mu * mu;
    const float rstd = rsqrtf(var + 1e-5f);

    const float4 gv = __ldg((const float4*)(g + c));
    const float4 bv = __ldg((const float4*)(bvec + c));
    const float t0 = (y0 - mu) * rstd * gv.x + bv.x;
    const float t1 = (y1 - mu) * rstd * gv.y + bv.y;
    const float t2 = (y2 - mu) * rstd * gv.z + bv.z;
    const float t3 = (y3 - mu) * rstd * gv.w + bv.w;

    const float4 e0 = __ldg((const float4*)(emb + 0 * HD + c));
    const float4 e1 = __ldg((const float4*)(emb + 1 * HD + c));
    const float4 e2 = __ldg((const float4*)(emb + 2 * HD + c));
    const float4 e3 = __ldg((const float4*)(emb + 3 * HD + c));

    float sc0, sc1, sc2, sc3;
    blk_reduce4(t0 * e0.x + t1 * e0.y + t2 * e0.z + t3 * e0.w,
                t0 * e1.x + t1 * e1.y + t2 * e1.z + t3 * e1.w,
                t0 * e2.x + t1 * e2.y + t2 * e2.z + t3 * e2.w,
                t0 * e3.x + t1 * e3.y + t2 * e3.z + t3 * e3.w,
                sbuf, sc0, sc1, sc2, sc3);

    const float4 mk = __ldg((const float4*)(masks + (size_t)row * 4));
    const float wn0 = (mk.x > 0.5f) ? expf(sc0) : 0.0f;
    const float wn1 = (mk.y > 0.5f) ? expf(sc1) : 0.0f;
    const float wn2 = (mk.z > 0.5f) ? expf(sc2) : 0.0f;
    const float wn3 = (mk.w > 0.5f) ? expf(sc3) : 0.0f;
    const float tot = wn0 + wn1 + wn2 + wn3;
    const float inv = (tot > 1e-8f) ? (1.0f / tot) : 1.0f;
    const float q0 = wn0 * inv, q1 = wn1 * inv, q2 = wn2 * inv, q3 = wn3 * inv;

    // gate: dot(fused, t) = q0*sc0 + q1*sc1 + q2*sc2 + q3*sc3  (exact identity)
    const float gsum = q0 * sc0 + q1 * sc1 + q2 * sc2 + q3 * sc3;
    const float gate = 1.0f / (1.0f + expf(-gsum * (1.0f / HD)));
    const float og = 1.0f - gate;

    const float f0 = q0 * e0.x + q1 * e1.x + q2 * e2.x + q3 * e3.x;
    const float f1 = q0 * e0.y + q1 * e1.y + q2 * e2.y + q3 * e3.y;
    const float f2 = q0 * e0.z + q1 * e1.z + q2 * e2.z + q3 * e3.z;
    const float f3 = q0 * e0.w + q1 * e1.w + q2 * e2.w + q3 * e3.w;

    const __half2 h01 = __floats2half2_rn(gate * f0 + og * t0, gate * f1 + og * t1);
    const __half2 h23 = __floats2half2_rn(gate * f2 + og * t2, gate * f3 + og * t3);
    __half2 hv[2] = {h01, h23};
    *(uint2*)(Fout + (size_t)row * HD + c) = *(uint2*)hv;
}

// ---------------------------------------------------------------------------
// Multi-scale windowed means along L, __half2 vectorized (one thread per h-pair)
// ---------------------------------------------------------------------------
#define H2 512   // HD / 2

__global__ __launch_bounds__(256) void multiscale_kernel(
    const __half2* __restrict__ F2, __half2* __restrict__ O2)
{
    const int L = LSEQ;
    const int SL = 128;

    const int gtid = blockIdx.x * 256 + threadIdx.x;
    const int h = gtid & (H2 - 1);
    const int rest = gtid >> 9;
    const int b = rest & 7;
    const int strip = rest >> 3;
    const int s0 = strip * SL;

    const __half2* base = F2 + (size_t)b * L * H2 + h;
    __half2* oA = O2 + (size_t)b * L * H2 + h;

    const float SW3  = (float)(1.0 / (1.0 + 1.0986122886681098));
    const float SW7  = (float)(1.0 / (1.0 + 1.9459101090932196));
    const float SW15 = (float)(1.0 / (1.0 + 2.7080502011022101));

    if (strip > 0 && strip < 31) {
        float2 ring[16];
        #pragma unroll
        for (int j = -8; j <= 6; ++j)
            ring[j & 15] = __half22float2(base[(size_t)(s0 + j) * H2]);

        float2 s3 = {0.f, 0.f}, s7 = {0.f, 0.f}, s15 = {0.f, 0.f};
        #pragma unroll
        for (int j = -8; j <= 6; ++j) {
            const float2 v = ring[j & 15];
            const int d = j + 1;
            if (d >= -7 && d <= 7) { s15.x += v.x; s15.y += v.y; }
            if (d >= -3 && d <= 3) { s7.x  += v.x; s7.y  += v.y; }
            if (d >= -1 && d <= 1) { s3.x  += v.x; s3.y  += v.y; }
        }

        const float w3 = SW3 * (1.0f / 3.0f);
        const float w7 = SW7 * (1.0f / 7.0f);
        const float w15 = SW15 * (1.0f / 15.0f);

        #pragma unroll 1
        for (int cch = 0; cch < SL; cch += 16) {
            #pragma unroll
            for (int i = 0; i < 16; ++i) {
                const int l = s0 + cch + i;
                const float2 nv = __half22float2(base[(size_t)(l + 7) * H2]);
                ring[(i + 7) & 15] = nv;
                s3.x  += ring[(i + 1) & 15].x - ring[(i - 2) & 15].x;
                s3.y  += ring[(i + 1) & 15].y - ring[(i - 2) & 15].y;
                s7.x  += ring[(i + 3) & 15].x - ring[(i - 4) & 15].x;
                s7.y  += ring[(i + 3) & 15].y - ring[(i - 4) & 15].y;
                s15.x += nv.x               - ring[(i - 8) & 15].x;
                s15.y += nv.y               - ring[(i - 8) & 15].y;
                const float2 s1 = ring[i & 15];
                const float ox = s1.x + s3.x * w3 + s7.x * w7 + s15.x * w15;
                const float oy = s1.y + s3.y * w3 + s7.y * w7 + s15.y * w15;
                oA[(size_t)l * H2] = __floats2half2_rn(ox, oy);
            }
        }
    } else {
        for (int l = s0; l < s0 + SL; ++l) {
            float2 s3 = {0.f, 0.f}, s7 = {0.f, 0.f}, s15 = {0.f, 0.f};
            #pragma unroll
            for (int j = -7; j <= 7; ++j) {
                const int p = l + j;
                float2 v = {0.f, 0.f};
                if (p >= 0 && p < L) v = __half22float2(base[(size_t)p * H2]);
                s15.x += v.x; s15.y += v.y;
                if (j >= -3 && j <= 3) { s7.x += v.x; s7.y += v.y; }
                if (j >= -1 && j <= 1) { s3.x += v.x; s3.y += v.y; }
            }
            const float2 s1 = __half22float2(base[(size_t)l * H2]);
            const float c3  = 1.0f / (float)(min(l + 2, L) - max(l - 1, 0));
            const float c7  = 1.0f / (float)(min(l + 4, L) - max(l - 3, 0));
            const float c15 = 1.0f / (float)(min(l + 8, L) - max(l - 7, 0));
            const float ox = s1.x + SW3 * s3.x * c3 + SW7 * s7.x * c7 + SW15 * s15.x * c15;
            const float oy = s1.y + SW3 * s3.y * c3 + SW7 * s7.y * c7 + SW15 * s15.y * c15;
            oA[(size_t)l * H2] = __floats2half2_rn(ox, oy);
        }
    }
}

// ---------------------------------------------------------------------------
// LN2 + residual (one block per row, fused dual reduction, fp16 Y input)
// ---------------------------------------------------------------------------
__global__ __launch_bounds__(256) void ln2_res_kernel(
    const __half* __restrict__ Y, const float* __restrict__ X,
    const float* __restrict__ g, const float* __restrict__ bvec,
    float* __restrict__ out)
{
    __shared__ float sbuf[56];
    const int row = blockIdx.x;
    const int c = threadIdx.x * 4;

    const uint2 yraw = *(const uint2*)(Y + (size_t)row * HD + c);
    const float2 ya = __half22float2(*(const __half2*)&yraw.x);
    const float2 yb = __half22float2(*(const __half2*)&yraw.y);
    const float y0 = ya.x, y1 = ya.y, y2 = yb.x, y3 = yb.y;

    float sum, sumsq;
    blk_reduce2(y0 + y1 + y2 + y3,
                y0 * y0 + y1 * y1 + y2 * y2 + y3 * y3,
                sbuf, sum, sumsq);
    const float mu   = sum * (1.0f / HD);
    const float var  = sumsq * (1.0f / HD) - mu * mu;
    const float rstd = rsqrtf(var + 1e-5f);

    const float4 gv = __ldg((const float4*)(g + c));
    const float4 bv = __ldg((const float4*)(bvec + c));
    const float4 xv = *(const float4*)(X + (size_t)row * HD + c);

    float4 o;
    o.x = (y0 - mu) * rstd * gv.x + bv.x + xv.x;
    o.y = (y1 - mu) * rstd * gv.y + bv.y + xv.y;
    o.z = (y2 - mu) * rstd * gv.z + bv.z + xv.z;
    o.w = (y3 - mu) * rstd * gv.w + bv.w + xv.w;
    *(float4*)(out + (size_t)row * HD + c) = o;
}

// ---------------------------------------------------------------------------
// Launcher
// ---------------------------------------------------------------------------
extern "C" void kernel_launch(void* const* d_in, const int* in_sizes, int n_in,
                              void* d_out, int out_size)
{
    const float* X   = (const float*)d_in[0];
    const float* msk = (const float*)d_in[1];
    const float* emb = (const float*)d_in[2];
    const float* ltw = (const float*)d_in[3];
    const float* ltb = (const float*)d_in[4];
    const float* g1  = (const float*)d_in[5];
    const float* b1  = (const float*)d_in[6];
    const float* ftw = (const float*)d_in[7];
    const float* ftb = (const float*)d_in[8];
    const float* g2  = (const float*)d_in[9];
    const float* b2  = (const float*)d_in[10];
    float* out = (float*)d_out;

    float *bufA, *bufB;
    __half *A2, *Wt1, *Wt2;
    cudaGetSymbolAddress((void**)&bufA, g_bufA);
    cudaGetSymbolAddress((void**)&bufB, g_bufB);
    cudaGetSymbolAddress((void**)&A2,  g_A2);
    cudaGetSymbolAddress((void**)&Wt1, g_Wt1);
    cudaGetSymbolAddress((void**)&Wt2, g_Wt2);
    __half* Y1h = (__half*)bufA;              // fp16 Y1
    __half* Fh  = (__half*)bufB;              // fp16 F
    __half* Y2h = (__half*)bufB + (size_t)MROWS * HD / 2;  // fp16 Y2 (2nd half)

    cudaFuncSetAttribute((const void*)gemm_mma_kernel<float>,
                         cudaFuncAttributeMaxDynamicSharedMemorySize, GEMM_SMEM);
    cudaFuncSetAttribute((const void*)gemm_mma_kernel<__half>,
                         cudaFuncAttributeMaxDynamicSharedMemorySize, GEMM_SMEM);

    const dim3 ggrid(HD / BN, MROWS / BM);   // (8, 256) = 2048 CTAs

    // weight transposes to fp16 (every call; deterministic)
    convW_kernel<<<(HD * HD) / 256, 256>>>(ltw, Wt1);
    convW_kernel<<<(HD * HD) / 256, 256>>>(ftw, Wt2);

    // 1) Y1 = X @ lt_w + lt_b   (fp16 out)
    convA_kernel<<<(MROWS * HD / 4) / 256, 256>>>(X, A2);
    gemm_mma_kernel<__half><<<ggrid, 128, GEMM_SMEM>>>(A2, Wt1, ltb, Y1h);
    // 2) F = fusion(LN1(Y1)) -> fp16
    ln1_fusion_kernel<<<MROWS, 256>>>(Y1h, msk, emb, g1, b1, Fh);
    // 3) agg = multiscale(F), half2-vectorized, fp16 in/out -> A2
    multiscale_kernel<<<(BDIM * H2 * 32) / 256, 256>>>(
        (const __half2*)Fh, (__half2*)A2);
    // 4) Y2 = agg @ ft_w + ft_b  (fp16 out)
    gemm_mma_kernel<__half><<<ggrid, 128, GEMM_SMEM>>>(A2, Wt2, ftb, Y2h);
    // 5) out = LN2(Y2) + X
    ln2_res_kernel<<<MROWS, 256>>>(Y2h, X, g2, b2, out);
}

// round 12
// speedup vs baseline: 1.4915x; 1.0082x over previous
#include <cuda_runtime.h>
#include <cuda_fp16.h>
#include <math.h>
#include <stdint.h>

// Problem shape (fixed by setup_inputs)
#define MROWS 32768          // B*L
#define BDIM  8
#define LSEQ  4096
#define HD    1024
#define NL    4
#define NCHK  32             // HD / BK
#define NCHK2 64             // two tiles back-to-back

// GEMM tiling: CTA 128x128, 4 warps (2x2), warp tile 64x64, BK=32
#define BM 128
#define BN 128
#define BK 32
#define NSTAGE 3
#define ROWB 80                           // (32+8) fp16 = 80 bytes per row
#define A_STG (BM * ROWB)                 // 10240
#define B_STG (BN * ROWB)                 // 10240
#define STG   (A_STG + B_STG)             // 20480
#define GEMM_SMEM (NSTAGE * STG)          // 61440 (x3 CTAs = 184KB <= 228KB)

// ---------------------------------------------------------------------------
// Scratch (device globals: allocation-free)
// ---------------------------------------------------------------------------
__device__ float g_bufA[(size_t)MROWS * HD];     // low half reused as fp16 Y1
__device__ float g_bufB[(size_t)MROWS * HD];     // fp16 F / fp16 Y2
__device__ __align__(256) __half g_A2[(size_t)MROWS * HD];    // fp16 A
__device__ __align__(256) __half g_Wt1[(size_t)HD * HD];      // lt_w^T fp16
__device__ __align__(256) __half g_Wt2[(size_t)HD * HD];      // ft_w^T fp16

// ---------------------------------------------------------------------------
// PTX helpers (sm_80-class features only: cp.async, ldmatrix, mma.sync)
// ---------------------------------------------------------------------------
__device__ __forceinline__ uint32_t smem_to_u32(const void* p) {
    uint32_t a;
    asm("{ .reg .u64 t; cvta.to.shared.u64 t, %1; cvt.u32.u64 %0, t; }" : "=r"(a) : "l"(p));
    return a;
}
__device__ __forceinline__ void cp_async16(uint32_t dst, const void* src) {
    asm volatile("cp.async.cg.shared.global [%0], [%1], 16;\n" :: "r"(dst), "l"(src) : "memory");
}
#define CP_COMMIT() asm volatile("cp.async.commit_group;" ::: "memory")
#define CP_WAIT1()  asm volatile("cp.async.wait_group 1;" ::: "memory")

__device__ __forceinline__ void ldsm_x4(uint32_t (&r)[4], uint32_t addr) {
    asm volatile("ldmatrix.sync.aligned.m8n8.x4.shared.b16 {%0,%1,%2,%3}, [%4];"
        : "=r"(r[0]), "=r"(r[1]), "=r"(r[2]), "=r"(r[3]) : "r"(addr));
}
__device__ __forceinline__ void mma16816(float (&c)[4],
                                         const uint32_t (&a)[4],
                                         uint32_t b0, uint32_t b1) {
    asm volatile(
        "mma.sync.aligned.m16n8k16.row.col.f32.f16.f16.f32 "
        "{%0,%1,%2,%3}, {%4,%5,%6,%7}, {%8,%9}, {%0,%1,%2,%3};"
        : "+f"(c[0]), "+f"(c[1]), "+f"(c[2]), "+f"(c[3])
        : "r"(a[0]), "r"(a[1]), "r"(a[2]), "r"(a[3]), "r"(b0), "r"(b1));
}

__device__ __forceinline__ float warp_sum(float v) {
    #pragma unroll
    for (int o = 16; o > 0; o >>= 1) v += __shfl_xor_sync(0xffffffffu, v, o);
    return v;
}

// ---- fused block reductions (256 threads, 8 warps), disjoint sbuf regions ----
__device__ __forceinline__ void blk_reduce2(float v1, float v2, float* sbuf,
                                            float& r1, float& r2)
{
    v1 = warp_sum(v1); v2 = warp_sum(v2);
    const int lane = threadIdx.x & 31, w = threadIdx.x >> 5;
    if (lane == 0) { sbuf[w] = v1; sbuf[8 + w] = v2; }
    __syncthreads();
    if (threadIdx.x < 16) {
        float x = sbuf[threadIdx.x];
        x += __shfl_xor_sync(0xffffu, x, 4);
        x += __shfl_xor_sync(0xffffu, x, 2);
        x += __shfl_xor_sync(0xffffu, x, 1);
        if ((threadIdx.x & 7) == 0) sbuf[16 + (threadIdx.x >> 3)] = x;
    }
    __syncthreads();
    r1 = sbuf[16]; r2 = sbuf[17];
}

__device__ __forceinline__ void blk_reduce4(float p0, float p1, float p2, float p3,
                                            float* sbuf,
                                            float& r0, float& r1, float& r2, float& r3)
{
    p0 = warp_sum(p0); p1 = warp_sum(p1); p2 = warp_sum(p2); p3 = warp_sum(p3);
    const int lane = threadIdx.x & 31, w = threadIdx.x >> 5;
    if (lane == 0) {
        sbuf[20 + w] = p0; sbuf[28 + w] = p1; sbuf[36 + w] = p2; sbuf[44 + w] = p3;
    }
    __syncthreads();
    if (threadIdx.x < 32) {
        float x = sbuf[20 + threadIdx.x];
        x += __shfl_xor_sync(0xffffffffu, x, 4);
        x += __shfl_xor_sync(0xffffffffu, x, 2);
        x += __shfl_xor_sync(0xffffffffu, x, 1);
        if ((threadIdx.x & 7) == 0) sbuf[52 + (threadIdx.x >> 3)] = x;
    }
    __syncthreads();
    r0 = sbuf[52]; r1 = sbuf[53]; r2 = sbuf[54]; r3 = sbuf[55];
}

// ---------------------------------------------------------------------------
// fp32 -> fp16 conversion of A [M, HD]
// ---------------------------------------------------------------------------
__global__ __launch_bounds__(256) void convA_kernel(
    const float* __restrict__ A, __half* __restrict__ A2)
{
    const size_t i = (size_t)blockIdx.x * 256 + threadIdx.x;
    const float4 v = *(const float4*)(A + i * 4);
    __half h[4];
    h[0] = __float2half_rn(v.x); h[1] = __float2half_rn(v.y);
    h[2] = __float2half_rn(v.z); h[3] = __float2half_rn(v.w);
    ((unsigned long long*)A2)[i] = *(const unsigned long long*)h;
}

// Both weights in one launch: W1,W2 [HD,HD] fp32 -> Wt1,Wt2 [n][k] fp16
__global__ __launch_bounds__(256) void convW2_kernel(
    const float* __restrict__ W1, __half* __restrict__ Wt1,
    const float* __restrict__ W2, __half* __restrict__ Wt2)
{
    const int which = blockIdx.x >= (HD * HD) / 256;
    const int idx = (blockIdx.x - which * ((HD * HD) / 256)) * 256 + threadIdx.x;
    const int n = idx & (HD - 1);
    const int k = idx >> 10;
    const float* W = which ? W2 : W1;
    __half* Wt = which ? Wt2 : Wt1;
    Wt[(size_t)n * HD + k] = __float2half_rn(W[(size_t)k * HD + n]);
}

// ---------------------------------------------------------------------------
// mma.sync GEMM, 2 M-tiles per CTA with a seamless 64-chunk pipeline:
// CTA 128x128, 4 warps (2x2), warp tile 64x64, BK=32, 3-stage ring runs
// continuously across the tile boundary (epilogue overlaps next tile's loads).
// ---------------------------------------------------------------------------
template <typename OutT>
__global__ __launch_bounds__(128, 3) void gemm_mma_kernel(
    const __half* __restrict__ A2,
    const __half* __restrict__ Wt,
    const float* __restrict__ bias,
    OutT* __restrict__ C)
{
    extern __shared__ char smem_raw[];
    const uint32_t sbase = smem_to_u32(smem_raw);

    const int tid = threadIdx.x;
    const int wid = tid >> 5;
    const int lane = tid & 31;
    const int m_base = blockIdx.y * (2 * BM);   // two tiles: m_base, m_base+BM
    const int n0 = blockIdx.x * BN;

    const int wm = (wid >> 1) * 64;
    const int wn = (wid & 1) * 64;

    const int lr = tid >> 2;             // 0..31
    const int lc = tid & 3;
    // B pointers fixed (same n0 for both tiles)
    const __half* gB[4];
    #pragma unroll
    for (int j = 0; j < 4; ++j)
        gB[j] = Wt + (size_t)(n0 + lr + 32 * j) * HD + lc * 8;
    // A base rows for the two tiles
    const __half* gA_t0 = A2 + (size_t)(m_base + lr) * HD + lc * 8;
    const __half* gA_t1 = gA_t0 + (size_t)BM * HD;

    const uint32_t sA_off = lr * ROWB + lc * 16;
    const uint32_t sB_off = A_STG + lr * ROWB + lc * 16;
    const uint32_t RSTEP32 = 32 * ROWB;
    const size_t   ARSTEP = (size_t)32 * HD;   // 32 rows in gmem

    const int lrow = lane & 15;
    const int lkof = (lane >> 4) * 16;
    const uint32_t aAddrBase = sbase + (wm + lrow) * ROWB + lkof;
    const uint32_t bAddrBase = sbase + A_STG + (wn + lrow) * ROWB + lkof;

    const int g = lane >> 2;
    const int t = lane & 3;

    float acc[4][8][4];
    #pragma unroll
    for (int i = 0; i < 4; ++i)
        #pragma unroll
        for (int j = 0; j < 8; ++j)
            #pragma unroll
            for (int q = 0; q < 4; ++q) acc[i][j][q] = 0.0f;

    // chunk-q load issue (q in [0,64): tile q>>5, local chunk q&31)
    auto issue = [&](int q, int stage) {
        const uint32_t sb = sbase + stage * STG;
        const size_t go = (size_t)(q & 31) * BK;
        const __half* gA = (q < NCHK) ? gA_t0 : gA_t1;
        #pragma unroll
        for (int j = 0; j < 4; ++j) {
            cp_async16(sb + sA_off + j * RSTEP32, gA + j * ARSTEP + go);
            cp_async16(sb + sB_off + j * RSTEP32, gB[j] + go);
        }
    };

    // prologue: chunks 0,1 into stages 0,1
    issue(0, 0); CP_COMMIT();
    issue(1, 1); CP_COMMIT();

    int s_c = 0;   // stage of chunk kc
    int s_q = 2;   // stage of chunk kc+2
    #pragma unroll 1
    for (int kc = 0; kc < NCHK2; ++kc) {
        CP_WAIT1();               // chunk kc landed (<=1 younger outstanding)
        __syncthreads();

        const int q = kc + 2;
        if (q < NCHK2) issue(q, s_q);
        CP_COMMIT();

        const uint32_t stg = s_c * STG;
        #pragma unroll
        for (int ks = 0; ks < 2; ++ks) {
            uint32_t a[4][4], b[4][4];
            const uint32_t kb = stg + ks * 32;
            #pragma unroll
            for (int i = 0; i < 4; ++i)
                ldsm_x4(a[i], aAddrBase + kb + i * (16 * ROWB));
            #pragma unroll
            for (int j = 0; j < 4; ++j)
                ldsm_x4(b[j], bAddrBase + kb + j * (16 * ROWB));
            #pragma unroll
            for (int i = 0; i < 4; ++i) {
                #pragma unroll
                for (int j = 0; j < 4; ++j) {
                    mma16816(acc[i][2 * j + 0], a[i], b[j][0], b[j][2]);
                    mma16816(acc[i][2 * j + 1], a[i], b[j][1], b[j][3]);
                }
            }
        }

        // tile boundary: store + reset accumulators (loads for next tile are
        // already in flight; pipeline never drains)
        if ((kc & (NCHK - 1)) == NCHK - 1) {
            const int m0 = m_base + (kc >> 5) * BM;
            #pragma unroll
            for (int i = 0; i < 4; ++i) {
                const int row = m0 + wm + i * 16 + g;
                #pragma unroll
                for (int j = 0; j < 8; ++j) {
                    const int col = n0 + wn + j * 8 + t * 2;
                    const float b0 = bias[col], b1 = bias[col + 1];
                    const float v00 = acc[i][j][0] + b0, v01 = acc[i][j][1] + b1;
                    const float v10 = acc[i][j][2] + b0, v11 = acc[i][j][3] + b1;
                    if (sizeof(OutT) == 4) {
                        *(float2*)((float*)C + (size_t)row * HD + col) = make_float2(v00, v01);
                        *(float2*)((float*)C + (size_t)(row + 8) * HD + col) = make_float2(v10, v11);
                    } else {
                        *(__half2*)((__half*)C + (size_t)row * HD + col) = __floats2half2_rn(v00, v01);
                        *(__half2*)((__half*)C + (size_t)(row + 8) * HD + col) = __floats2half2_rn(v10, v11);
                    }
                    acc[i][j][0] = 0.f; acc[i][j][1] = 0.f;
                    acc[i][j][2] = 0.f; acc[i][j][3] = 0.f;
                }
            }
        }

        if (++s_c == NSTAGE) s_c = 0;
        if (++s_q == NSTAGE) s_q = 0;
    }
}

// ---------------------------------------------------------------------------
// LN1 + hierarchical fusion (one block per row; fp16 Y1 input; gate via
// algebraic identity dot(fused,t) = sum_n q_n * sc_n)
// ---------------------------------------------------------------------------
__global__ __launch_bounds__(256) void ln1_fusion_kernel(
    const __half* __restrict__ Y, const float* __restrict__ masks,
    const float* __restrict__ emb,
    const float* __restrict__ g, const float* __restrict__ bvec,
    __half* __restrict__ Fout)
{
    __shared__ float sbuf[56];

    const int row = blockIdx.x;
    const int c = threadIdx.x * 4;

    const uint2 yraw = *(const uint2*)(Y + (size_t)row * HD + c);
    const float2 ya = __half22float2(*(const __half2*)&yraw.x);
    const float2 yb = __half22float2(*(const __half2*)&yraw.y);
    const float y0 = ya.x, y1 = ya.y, y2 = yb.x, y3 = yb.y;

    float sum, sumsq;
    blk_reduce2(y0 + y1 + y2 + y3,
                y0 * y0 + y1 * y1 + y2 * y2 + y3 * y3,
                sbuf, sum, sumsq);
    const float mu   = sum * (1.0f / HD);
    const float var  = sumsq * (1.0f / HD) - mu * mu;
    const float rstd = rsqrtf(var + 1e-5f);

    const float4 gv = __ldg((const float4*)(g + c));
    const float4 bv = __ldg((const float4*)(bvec + c));
    const float t0 = (y0 - mu) * rstd * gv.x + bv.x;
    const float t1 = (y1 - mu) * rstd * gv.y + bv.y;
    const float t2 = (y2 - mu) * rstd * gv.z + bv.z;
    const float t3 = (y3 - mu) * rstd * gv.w + bv.w;

    const float4 e0 = __ldg((const float4*)(emb + 0 * HD + c));
    const float4 e1 = __ldg((const float4*)(emb + 1 * HD + c));
    const float4 e2 = __ldg((const float4*)(emb + 2 * HD + c));
    const float4 e3 = __ldg((const float4*)(emb + 3 * HD + c));

    float sc0, sc1, sc2, sc3;
    blk_reduce4(t0 * e0.x + t1 * e0.y + t2 * e0.z + t3 * e0.w,
                t0 * e1.x + t1 * e1.y + t2 * e1.z + t3 * e1.w,
                t0 * e2.x + t1 * e2.y + t2 * e2.z + t3 * e2.w,
                t0 * e3.x + t1 * e3.y + t2 * e3.z + t3 * e3.w,
                sbuf, sc0, sc1, sc2, sc3);

    const float4 mk = __ldg((const float4*)(masks + (size_t)row * 4));
    const float wn0 = (mk.x > 0.5f) ? expf(sc0) : 0.0f;
    const float wn1 = (mk.y > 0.5f) ? expf(sc1) : 0.0f;
    const float wn2 = (mk.z > 0.5f) ? expf(sc2) : 0.0f;
    const float wn3 = (mk.w > 0.5f) ? expf(sc3) : 0.0f;
    const float tot = wn0 + wn1 + wn2 + wn3;
    const float inv = (tot > 1e-8f) ? (1.0f / tot) : 1.0f;
    const float q0 = wn0 * inv, q1 = wn1 * inv, q2 = wn2 * inv, q3 = wn3 * inv;

    const float gsum = q0 * sc0 + q1 * sc1 + q2 * sc2 + q3 * sc3;
    const float gate = 1.0f / (1.0f + expf(-gsum * (1.0f / HD)));
    const float og = 1.0f - gate;

    const float f0 = q0 * e0.x + q1 * e1.x + q2 * e2.x + q3 * e3.x;
    const float f1 = q0 * e0.y + q1 * e1.y + q2 * e2.y + q3 * e3.y;
    const float f2 = q0 * e0.z + q1 * e1.z + q2 * e2.z + q3 * e3.z;
    const float f3 = q0 * e0.w + q1 * e1.w + q2 * e2.w + q3 * e3.w;

    const __half2 h01 = __floats2half2_rn(gate * f0 + og * t0, gate * f1 + og * t1);
    const __half2 h23 = __floats2half2_rn(gate * f2 + og * t2, gate * f3 + og * t3);
    __half2 hv[2] = {h01, h23};
    *(uint2*)(Fout + (size_t)row * HD + c) = *(uint2*)hv;
}

// ---------------------------------------------------------------------------
// Multi-scale windowed means along L, __half2 vectorized (one thread per h-pair)
// ---------------------------------------------------------------------------
#define H2 512   // HD / 2

__global__ __launch_bounds__(256) void multiscale_kernel(
    const __half2* __restrict__ F2, __half2* __restrict__ O2)
{
    const int L = LSEQ;
    const int SL = 128;

    const int gtid = blockIdx.x * 256 + threadIdx.x;
    const int h = gtid & (H2 - 1);
    const int rest = gtid >> 9;
    const int b = rest & 7;
    const int strip = rest >> 3;
    const int s0 = strip * SL;

    const __half2* base = F2 + (size_t)b * L * H2 + h;
    __half2* oA = O2 + (size_t)b * L * H2 + h;

    const float SW3  = (float)(1.0 / (1.0 + 1.0986122886681098));
    const float SW7  = (float)(1.0 / (1.0 + 1.9459101090932196));
    const float SW15 = (float)(1.0 / (1.0 + 2.7080502011022101));

    if (strip > 0 && strip < 31) {
        float2 ring[16];
        #pragma unroll
        for (int j = -8; j <= 6; ++j)
            ring[j & 15] = __half22float2(base[(size_t)(s0 + j) * H2]);

        float2 s3 = {0.f, 0.f}, s7 = {0.f, 0.f}, s15 = {0.f, 0.f};
        #pragma unroll
        for (int j = -8; j <= 6; ++j) {
            const float2 v = ring[j & 15];
            const int d = j + 1;
            if (d >= -7 && d <= 7) { s15.x += v.x; s15.y += v.y; }
            if (d >= -3 && d <= 3) { s7.x  += v.x; s7.y  += v.y; }
            if (d >= -1 && d <= 1) { s3.x  += v.x; s3.y  += v.y; }
        }

        const float w3 = SW3 * (1.0f / 3.0f);
        const float w7 = SW7 * (1.0f / 7.0f);
        const float w15 = SW15 * (1.0f / 15.0f);

        #pragma unroll 1
        for (int cch = 0; cch < SL; cch += 16) {
            #pragma unroll
            for (int i = 0; i < 16; ++i) {
                const int l = s0 + cch + i;
                const float2 nv = __half22float2(base[(size_t)(l + 7) * H2]);
                ring[(i + 7) & 15] = nv;
                s3.x  += ring[(i + 1) & 15].x - ring[(i - 2) & 15].x;
                s3.y  += ring[(i + 1) & 15].y - ring[(i - 2) & 15].y;
                s7.x  += ring[(i + 3) & 15].x - ring[(i - 4) & 15].x;
                s7.y  += ring[(i + 3) & 15].y - ring[(i - 4) & 15].y;
                s15.x += nv.x               - ring[(i - 8) & 15].x;
                s15.y += nv.y               - ring[(i - 8) & 15].y;
                const float2 s1 = ring[i & 15];
                const float ox = s1.x + s3.x * w3 + s7.x * w7 + s15.x * w15;
                const float oy = s1.y + s3.y * w3 + s7.y * w7 + s15.y * w15;
                oA[(size_t)l * H2] = __floats2half2_rn(ox, oy);
            }
        }
    } else {
        for (int l = s0; l < s0 + SL; ++l) {
            float2 s3 = {0.f, 0.f}, s7 = {0.f, 0.f}, s15 = {0.f, 0.f};
            #pragma unroll
            for (int j = -7; j <= 7; ++j) {
                const int p = l + j;
                float2 v = {0.f, 0.f};
                if (p >= 0 && p < L) v = __half22float2(base[(size_t)p * H2]);
                s15.x += v.x; s15.y += v.y;
                if (j >= -3 && j <= 3) { s7.x += v.x; s7.y += v.y; }
                if (j >= -1 && j <= 1) { s3.x += v.x; s3.y += v.y; }
            }
            const float2 s1 = __half22float2(base[(size_t)l * H2]);
            const float c3  = 1.0f / (float)(min(l + 2, L) - max(l - 1, 0));
            const float c7  = 1.0f / (float)(min(l + 4, L) - max(l - 3, 0));
            const float c15 = 1.0f / (float)(min(l + 8, L) - max(l - 7, 0));
            const float ox = s1.x + SW3 * s3.x * c3 + SW7 * s7.x * c7 + SW15 * s15.x * c15;
            const float oy = s1.y + SW3 * s3.y * c3 + SW7 * s7.y * c7 + SW15 * s15.y * c15;
            oA[(size_t)l * H2] = __floats2half2_rn(ox, oy);
        }
    }
}

// ---------------------------------------------------------------------------
// LN2 + residual (one block per row, fused dual reduction, fp16 Y input)
// ---------------------------------------------------------------------------
__global__ __launch_bounds__(256) void ln2_res_kernel(
    const __half* __restrict__ Y, const float* __restrict__ X,
    const float* __restrict__ g, const float* __restrict__ bvec,
    float* __restrict__ out)
{
    __shared__ float sbuf[56];
    const int row = blockIdx.x;
    const int c = threadIdx.x * 4;

    const uint2 yraw = *(const uint2*)(Y + (size_t)row * HD + c);
    const float2 ya = __half22float2(*(const __half2*)&yraw.x);
    const float2 yb = __half22float2(*(const __half2*)&yraw.y);
    const float y0 = ya.x, y1 = ya.y, y2 = yb.x, y3 = yb.y;

    float sum, sumsq;
    blk_reduce2(y0 + y1 + y2 + y3,
                y0 * y0 + y1 * y1 + y2 * y2 + y3 * y3,
                sbuf, sum, sumsq);
    const float mu   = sum * (1.0f / HD);
    const float var  = sumsq * (1.0f / HD) - mu * mu;
    const float rstd = rsqrtf(var + 1e-5f);

    const float4 gv = __ldg((const float4*)(g + c));
    const float4 bv = __ldg((const float4*)(bvec + c));
    const float4 xv = *(const float4*)(X + (size_t)row * HD + c);

    float4 o;
    o.x = (y0 - mu) * rstd * gv.x + bv.x + xv.x;
    o.y = (y1 - mu) * rstd * gv.y + bv.y + xv.y;
    o.z = (y2 - mu) * rstd * gv.z + bv.z + xv.z;
    o.w = (y3 - mu) * rstd * gv.w + bv.w + xv.w;
    *(float4*)(out + (size_t)row * HD + c) = o;
}

// ---------------------------------------------------------------------------
// Launcher
// ---------------------------------------------------------------------------
extern "C" void kernel_launch(void* const* d_in, const int* in_sizes, int n_in,
                              void* d_out, int out_size)
{
    const float* X   = (const float*)d_in[0];
    const float* msk = (const float*)d_in[1];
    const float* emb = (const float*)d_in[2];
    const float* ltw = (const float*)d_in[3];
    const float* ltb = (const float*)d_in[4];
    const float* g1  = (const float*)d_in[5];
    const float* b1  = (const float*)d_in[6];
    const float* ftw = (const float*)d_in[7];
    const float* ftb = (const float*)d_in[8];
    const float* g2  = (const float*)d_in[9];
    const float* b2  = (const float*)d_in[10];
    float* out = (float*)d_out;

    float *bufA, *bufB;
    __half *A2, *Wt1, *Wt2;
    cudaGetSymbolAddress((void**)&bufA, g_bufA);
    cudaGetSymbolAddress((void**)&bufB, g_bufB);
    cudaGetSymbolAddress((void**)&A2,  g_A2);
    cudaGetSymbolAddress((void**)&Wt1, g_Wt1);
    cudaGetSymbolAddress((void**)&Wt2, g_Wt2);
    __half* Y1h = (__half*)bufA;              // fp16 Y1
    __half* Fh  = (__half*)bufB;              // fp16 F
    __half* Y2h = (__half*)bufB + (size_t)MROWS * HD / 2;  // fp16 Y2 (2nd half)

    cudaFuncSetAttribute((const void*)gemm_mma_kernel<float>,
                         cudaFuncAttributeMaxDynamicSharedMemorySize, GEMM_SMEM);
    cudaFuncSetAttribute((const void*)gemm_mma_kernel<__half>,
                         cudaFuncAttributeMaxDynamicSharedMemorySize, GEMM_SMEM);

    const dim3 ggrid(HD / BN, MROWS / (2 * BM));   // (8, 128) = 1024 CTAs, 2 tiles each

    // both weight transposes in one launch
    convW2_kernel<<<2 * (HD * HD) / 256, 256>>>(ltw, Wt1, ftw, Wt2);

    // 1) Y1 = X @ lt_w + lt_b   (fp16 out)
    convA_kernel<<<(MROWS * HD / 4) / 256, 256>>>(X, A2);
    gemm_mma_kernel<__half><<<ggrid, 128, GEMM_SMEM>>>(A2, Wt1, ltb, Y1h);
    // 2) F = fusion(LN1(Y1)) -> fp16
    ln1_fusion_kernel<<<MROWS, 256>>>(Y1h, msk, emb, g1, b1, Fh);
    // 3) agg = multiscale(F), half2-vectorized, fp16 in/out -> A2
    multiscale_kernel<<<(BDIM * H2 * 32) / 256, 256>>>(
        (const __half2*)Fh, (__half2*)A2);
    // 4) Y2 = agg @ ft_w + ft_b  (fp16 out)
    gemm_mma_kernel<__half><<<ggrid, 128, GEMM_SMEM>>>(A2, Wt2, ftb, Y2h);
    // 5) out = LN2(Y2) + X
    ln2_res_kernel<<<MROWS, 256>>>(Y2h, X, g2, b2, out);
}

// round 13
// speedup vs baseline: 1.5375x; 1.0308x over previous
#include <cuda_runtime.h>
#include <cuda_fp16.h>
#include <math.h>
#include <stdint.h>

// Problem shape (fixed by setup_inputs)
#define MROWS 32768          // B*L
#define BDIM  8
#define LSEQ  4096
#define HD    1024
#define NL    4
#define NCHK  32             // HD / BK
#define NCHK2 64             // two tiles back-to-back
#define RPB   4              // rows per LN block

// GEMM tiling: CTA 128x128, 4 warps (2x2), warp tile 64x64, BK=32
#define BM 128
#define BN 128
#define BK 32
#define NSTAGE 3
#define ROWB 80                           // (32+8) fp16 = 80 bytes per row
#define A_STG (BM * ROWB)                 // 10240
#define B_STG (BN * ROWB)                 // 10240
#define STG   (A_STG + B_STG)             // 20480
#define GEMM_SMEM (NSTAGE * STG)          // 61440 (x3 CTAs = 184KB <= 228KB)

// ---------------------------------------------------------------------------
// Scratch (device globals: allocation-free)
// ---------------------------------------------------------------------------
__device__ float g_bufA[(size_t)MROWS * HD];     // low half reused as fp16 Y1
__device__ float g_bufB[(size_t)MROWS * HD];     // fp16 F / fp16 Y2
__device__ __align__(256) __half g_A2[(size_t)MROWS * HD];    // fp16 A
__device__ __align__(256) __half g_Wt1[(size_t)HD * HD];      // lt_w^T fp16
__device__ __align__(256) __half g_Wt2[(size_t)HD * HD];      // ft_w^T fp16

// ---------------------------------------------------------------------------
// PTX helpers (sm_80-class features only: cp.async, ldmatrix, mma.sync)
// ---------------------------------------------------------------------------
__device__ __forceinline__ uint32_t smem_to_u32(const void* p) {
    uint32_t a;
    asm("{ .reg .u64 t; cvta.to.shared.u64 t, %1; cvt.u32.u64 %0, t; }" : "=r"(a) : "l"(p));
    return a;
}
__device__ __forceinline__ void cp_async16(uint32_t dst, const void* src) {
    asm volatile("cp.async.cg.shared.global [%0], [%1], 16;\n" :: "r"(dst), "l"(src) : "memory");
}
#define CP_COMMIT() asm volatile("cp.async.commit_group;" ::: "memory")
#define CP_WAIT1()  asm volatile("cp.async.wait_group 1;" ::: "memory")

__device__ __forceinline__ void ldsm_x4(uint32_t (&r)[4], uint32_t addr) {
    asm volatile("ldmatrix.sync.aligned.m8n8.x4.shared.b16 {%0,%1,%2,%3}, [%4];"
        : "=r"(r[0]), "=r"(r[1]), "=r"(r[2]), "=r"(r[3]) : "r"(addr));
}
__device__ __forceinline__ void mma16816(float (&c)[4],
                                         const uint32_t (&a)[4],
                                         uint32_t b0, uint32_t b1) {
    asm volatile(
        "mma.sync.aligned.m16n8k16.row.col.f32.f16.f16.f32 "
        "{%0,%1,%2,%3}, {%4,%5,%6,%7}, {%8,%9}, {%0,%1,%2,%3};"
        : "+f"(c[0]), "+f"(c[1]), "+f"(c[2]), "+f"(c[3])
        : "r"(a[0]), "r"(a[1]), "r"(a[2]), "r"(a[3]), "r"(b0), "r"(b1));
}

__device__ __forceinline__ float warp_sum(float v) {
    #pragma unroll
    for (int o = 16; o > 0; o >>= 1) v += __shfl_xor_sync(0xffffffffu, v, o);
    return v;
}

// N simultaneous block-wide sums with ONE store+barrier round (256 thr, 8 warps)
template <int N>
__device__ __forceinline__ void blk_reduceN(float (&v)[N], float* sbuf)
{
    #pragma unroll
    for (int k = 0; k < N; ++k) v[k] = warp_sum(v[k]);
    const int lane = threadIdx.x & 31, w = threadIdx.x >> 5;
    if (lane == 0) {
        #pragma unroll
        for (int k = 0; k < N; ++k) sbuf[k * 8 + w] = v[k];
    }
    __syncthreads();
    if (threadIdx.x < 8 * N) {                       // N<=16 -> <=128 threads
        float x = sbuf[threadIdx.x];                 // aligned groups of 8
        x += __shfl_xor_sync(0xffffffffu, x, 4);
        x += __shfl_xor_sync(0xffffffffu, x, 2);
        x += __shfl_xor_sync(0xffffffffu, x, 1);
        if ((threadIdx.x & 7) == 0) sbuf[8 * N + (threadIdx.x >> 3)] = x;
    }
    __syncthreads();
    #pragma unroll
    for (int k = 0; k < N; ++k) v[k] = sbuf[8 * N + k];
}

// ---------------------------------------------------------------------------
// fp32 -> fp16 conversion of A [M, HD]
// ---------------------------------------------------------------------------
__global__ __launch_bounds__(256) void convA_kernel(
    const float* __restrict__ A, __half* __restrict__ A2)
{
    const size_t i = (size_t)blockIdx.x * 256 + threadIdx.x;
    const float4 v = *(const float4*)(A + i * 4);
    __half h[4];
    h[0] = __float2half_rn(v.x); h[1] = __float2half_rn(v.y);
    h[2] = __float2half_rn(v.z); h[3] = __float2half_rn(v.w);
    ((unsigned long long*)A2)[i] = *(const unsigned long long*)h;
}

// Both weights in one launch: W1,W2 [HD,HD] fp32 -> Wt1,Wt2 [n][k] fp16
__global__ __launch_bounds__(256) void convW2_kernel(
    const float* __restrict__ W1, __half* __restrict__ Wt1,
    const float* __restrict__ W2, __half* __restrict__ Wt2)
{
    const int which = blockIdx.x >= (HD * HD) / 256;
    const int idx = (blockIdx.x - which * ((HD * HD) / 256)) * 256 + threadIdx.x;
    const int n = idx & (HD - 1);
    const int k = idx >> 10;
    const float* W = which ? W2 : W1;
    __half* Wt = which ? Wt2 : Wt1;
    Wt[(size_t)n * HD + k] = __float2half_rn(W[(size_t)k * HD + n]);
}

// ---------------------------------------------------------------------------
// mma.sync GEMM (UNCHANGED from round 12): 2 M-tiles per CTA, seamless
// 64-chunk pipeline, CTA 128x128, 4 warps, 64x64 warp tiles, 3 stages.
// ---------------------------------------------------------------------------
template <typename OutT>
__global__ __launch_bounds__(128, 3) void gemm_mma_kernel(
    const __half* __restrict__ A2,
    const __half* __restrict__ Wt,
    const float* __restrict__ bias,
    OutT* __restrict__ C)
{
    extern __shared__ char smem_raw[];
    const uint32_t sbase = smem_to_u32(smem_raw);

    const int tid = threadIdx.x;
    const int wid = tid >> 5;
    const int lane = tid & 31;
    const int m_base = blockIdx.y * (2 * BM);
    const int n0 = blockIdx.x * BN;

    const int wm = (wid >> 1) * 64;
    const int wn = (wid & 1) * 64;

    const int lr = tid >> 2;
    const int lc = tid & 3;
    const __half* gB[4];
    #pragma unroll
    for (int j = 0; j < 4; ++j)
        gB[j] = Wt + (size_t)(n0 + lr + 32 * j) * HD + lc * 8;
    const __half* gA_t0 = A2 + (size_t)(m_base + lr) * HD + lc * 8;
    const __half* gA_t1 = gA_t0 + (size_t)BM * HD;

    const uint32_t sA_off = lr * ROWB + lc * 16;
    const uint32_t sB_off = A_STG + lr * ROWB + lc * 16;
    const uint32_t RSTEP32 = 32 * ROWB;
    const size_t   ARSTEP = (size_t)32 * HD;

    const int lrow = lane & 15;
    const int lkof = (lane >> 4) * 16;
    const uint32_t aAddrBase = sbase + (wm + lrow) * ROWB + lkof;
    const uint32_t bAddrBase = sbase + A_STG + (wn + lrow) * ROWB + lkof;

    const int g = lane >> 2;
    const int t = lane & 3;

    float acc[4][8][4];
    #pragma unroll
    for (int i = 0; i < 4; ++i)
        #pragma unroll
        for (int j = 0; j < 8; ++j)
            #pragma unroll
            for (int q = 0; q < 4; ++q) acc[i][j][q] = 0.0f;

    auto issue = [&](int q, int stage) {
        const uint32_t sb = sbase + stage * STG;
        const size_t go = (size_t)(q & 31) * BK;
        const __half* gA = (q < NCHK) ? gA_t0 : gA_t1;
        #pragma unroll
        for (int j = 0; j < 4; ++j) {
            cp_async16(sb + sA_off + j * RSTEP32, gA + j * ARSTEP + go);
            cp_async16(sb + sB_off + j * RSTEP32, gB[j] + go);
        }
    };

    issue(0, 0); CP_COMMIT();
    issue(1, 1); CP_COMMIT();

    int s_c = 0;
    int s_q = 2;
    #pragma unroll 1
    for (int kc = 0; kc < NCHK2; ++kc) {
        CP_WAIT1();
        __syncthreads();

        const int q = kc + 2;
        if (q < NCHK2) issue(q, s_q);
        CP_COMMIT();

        const uint32_t stg = s_c * STG;
        #pragma unroll
        for (int ks = 0; ks < 2; ++ks) {
            uint32_t a[4][4], b[4][4];
            const uint32_t kb = stg + ks * 32;
            #pragma unroll
            for (int i = 0; i < 4; ++i)
                ldsm_x4(a[i], aAddrBase + kb + i * (16 * ROWB));
            #pragma unroll
            for (int j = 0; j < 4; ++j)
                ldsm_x4(b[j], bAddrBase + kb + j * (16 * ROWB));
            #pragma unroll
            for (int i = 0; i < 4; ++i) {
                #pragma unroll
                for (int j = 0; j < 4; ++j) {
                    mma16816(acc[i][2 * j + 0], a[i], b[j][0], b[j][2]);
                    mma16816(acc[i][2 * j + 1], a[i], b[j][1], b[j][3]);
                }
            }
        }

        if ((kc & (NCHK - 1)) == NCHK - 1) {
            const int m0 = m_base + (kc >> 5) * BM;
            #pragma unroll
            for (int i = 0; i < 4; ++i) {
                const int row = m0 + wm + i * 16 + g;
                #pragma unroll
                for (int j = 0; j < 8; ++j) {
                    const int col = n0 + wn + j * 8 + t * 2;
                    const float b0 = bias[col], b1 = bias[col + 1];
                    const float v00 = acc[i][j][0] + b0, v01 = acc[i][j][1] + b1;
                    const float v10 = acc[i][j][2] + b0, v11 = acc[i][j][3] + b1;
                    if (sizeof(OutT) == 4) {
                        *(float2*)((float*)C + (size_t)row * HD + col) = make_float2(v00, v01);
                        *(float2*)((float*)C + (size_t)(row + 8) * HD + col) = make_float2(v10, v11);
                    } else {
                        *(__half2*)((__half*)C + (size_t)row * HD + col) = __floats2half2_rn(v00, v01);
                        *(__half2*)((__half*)C + (size_t)(row + 8) * HD + col) = __floats2half2_rn(v10, v11);
                    }
                    acc[i][j][0] = 0.f; acc[i][j][1] = 0.f;
                    acc[i][j][2] = 0.f; acc[i][j][3] = 0.f;
                }
            }
        }

        if (++s_c == NSTAGE) s_c = 0;
        if (++s_q == NSTAGE) s_q = 0;
    }
}

// ---------------------------------------------------------------------------
// LN1 + hierarchical fusion: 4 rows per block, constants loaded once,
// batched reductions (1 barrier-pair per row on average).
// ---------------------------------------------------------------------------
__global__ __launch_bounds__(256) void ln1_fusion_kernel(
    const __half* __restrict__ Y, const float* __restrict__ masks,
    const float* __restrict__ emb,
    const float* __restrict__ g, const float* __restrict__ bvec,
    __half* __restrict__ Fout)
{
    __shared__ float sbuf[144];

    const int row0 = blockIdx.x * RPB;
    const int c = threadIdx.x * 4;

    const float4 gv = __ldg((const float4*)(g + c));
    const float4 bv = __ldg((const float4*)(bvec + c));
    const float4 e0 = __ldg((const float4*)(emb + 0 * HD + c));
    const float4 e1 = __ldg((const float4*)(emb + 1 * HD + c));
    const float4 e2 = __ldg((const float4*)(emb + 2 * HD + c));
    const float4 e3 = __ldg((const float4*)(emb + 3 * HD + c));

    // load 4 rows, accumulate sums
    float y[RPB][4];
    float v8[8];
    #pragma unroll
    for (int r = 0; r < RPB; ++r) {
        const uint2 yraw = *(const uint2*)(Y + (size_t)(row0 + r) * HD + c);
        const float2 ya = __half22float2(*(const __half2*)&yraw.x);
        const float2 yb = __half22float2(*(const __half2*)&yraw.y);
        y[r][0] = ya.x; y[r][1] = ya.y; y[r][2] = yb.x; y[r][3] = yb.y;
        v8[r]       = ya.x + ya.y + yb.x + yb.y;
        v8[RPB + r] = ya.x * ya.x + ya.y * ya.y + yb.x * yb.x + yb.y * yb.y;
    }
    blk_reduceN<8>(v8, sbuf);

    // LN per row (overwrite y with t), accumulate 16 score partials
    float v16[16];
    #pragma unroll
    for (int r = 0; r < RPB; ++r) {
        const float mu   = v8[r] * (1.0f / HD);
        const float var  = v8[RPB + r] * (1.0f / HD) - mu * mu;
        const float rstd = rsqrtf(var + 1e-5f);
        y[r][0] = (y[r][0] - mu) * rstd * gv.x + bv.x;
        y[r][1] = (y[r][1] - mu) * rstd * gv.y + bv.y;
        y[r][2] = (y[r][2] - mu) * rstd * gv.z + bv.z;
        y[r][3] = (y[r][3] - mu) * rstd * gv.w + bv.w;
        v16[r * 4 + 0] = y[r][0] * e0.x + y[r][1] * e0.y + y[r][2] * e0.z + y[r][3] * e0.w;
        v16[r * 4 + 1] = y[r][0] * e1.x + y[r][1] * e1.y + y[r][2] * e1.z + y[r][3] * e1.w;
        v16[r * 4 + 2] = y[r][0] * e2.x + y[r][1] * e2.y + y[r][2] * e2.z + y[r][3] * e2.w;
        v16[r * 4 + 3] = y[r][0] * e3.x + y[r][1] * e3.y + y[r][2] * e3.z + y[r][3] * e3.w;
    }
    blk_reduceN<16>(v16, sbuf);

    // per-row epilogue
    #pragma unroll
    for (int r = 0; r < RPB; ++r) {
        const float sc0 = v16[r * 4 + 0], sc1 = v16[r * 4 + 1];
        const float sc2 = v16[r * 4 + 2], sc3 = v16[r * 4 + 3];
        const float4 mk = __ldg((const float4*)(masks + (size_t)(row0 + r) * 4));
        const float wn0 = (mk.x > 0.5f) ? expf(sc0) : 0.0f;
        const float wn1 = (mk.y > 0.5f) ? expf(sc1) : 0.0f;
        const float wn2 = (mk.z > 0.5f) ? expf(sc2) : 0.0f;
        const float wn3 = (mk.w > 0.5f) ? expf(sc3) : 0.0f;
        const float tot = wn0 + wn1 + wn2 + wn3;
        const float inv = (tot > 1e-8f) ? (1.0f / tot) : 1.0f;
        const float q0 = wn0 * inv, q1 = wn1 * inv, q2 = wn2 * inv, q3 = wn3 * inv;

        const float gsum = q0 * sc0 + q1 * sc1 + q2 * sc2 + q3 * sc3;
        const float gate = 1.0f / (1.0f + expf(-gsum * (1.0f / HD)));
        const float og = 1.0f - gate;

        const float f0 = q0 * e0.x + q1 * e1.x + q2 * e2.x + q3 * e3.x;
        const float f1 = q0 * e0.y + q1 * e1.y + q2 * e2.y + q3 * e3.y;
        const float f2 = q0 * e0.z + q1 * e1.z + q2 * e2.z + q3 * e3.z;
        const float f3 = q0 * e0.w + q1 * e1.w + q2 * e2.w + q3 * e3.w;

        const __half2 h01 = __floats2half2_rn(gate * f0 + og * y[r][0],
                                              gate * f1 + og * y[r][1]);
        const __half2 h23 = __floats2half2_rn(gate * f2 + og * y[r][2],
                                              gate * f3 + og * y[r][3]);
        __half2 hv[2] = {h01, h23};
        *(uint2*)(Fout + (size_t)(row0 + r) * HD + c) = *(uint2*)hv;
    }
}

// ---------------------------------------------------------------------------
// Multi-scale windowed means along L, __half2 vectorized (one thread per h-pair)
// ---------------------------------------------------------------------------
#define H2 512   // HD / 2

__global__ __launch_bounds__(256) void multiscale_kernel(
    const __half2* __restrict__ F2, __half2* __restrict__ O2)
{
    const int L = LSEQ;
    const int SL = 128;

    const int gtid = blockIdx.x * 256 + threadIdx.x;
    const int h = gtid & (H2 - 1);
    const int rest = gtid >> 9;
    const int b = rest & 7;
    const int strip = rest >> 3;
    const int s0 = strip * SL;

    const __half2* base = F2 + (size_t)b * L * H2 + h;
    __half2* oA = O2 + (size_t)b * L * H2 + h;

    const float SW3  = (float)(1.0 / (1.0 + 1.0986122886681098));
    const float SW7  = (float)(1.0 / (1.0 + 1.9459101090932196));
    const float SW15 = (float)(1.0 / (1.0 + 2.7080502011022101));

    if (strip > 0 && strip < 31) {
        float2 ring[16];
        #pragma unroll
        for (int j = -8; j <= 6; ++j)
            ring[j & 15] = __half22float2(base[(size_t)(s0 + j) * H2]);

        float2 s3 = {0.f, 0.f}, s7 = {0.f, 0.f}, s15 = {0.f, 0.f};
        #pragma unroll
        for (int j = -8; j <= 6; ++j) {
            const float2 v = ring[j & 15];
            const int d = j + 1;
            if (d >= -7 && d <= 7) { s15.x += v.x; s15.y += v.y; }
            if (d >= -3 && d <= 3) { s7.x  += v.x; s7.y  += v.y; }
            if (d >= -1 && d <= 1) { s3.x  += v.x; s3.y  += v.y; }
        }

        const float w3 = SW3 * (1.0f / 3.0f);
        const float w7 = SW7 * (1.0f / 7.0f);
        const float w15 = SW15 * (1.0f / 15.0f);

        #pragma unroll 1
        for (int cch = 0; cch < SL; cch += 16) {
            #pragma unroll
            for (int i = 0; i < 16; ++i) {
                const int l = s0 + cch + i;
                const float2 nv = __half22float2(base[(size_t)(l + 7) * H2]);
                ring[(i + 7) & 15] = nv;
                s3.x  += ring[(i + 1) & 15].x - ring[(i - 2) & 15].x;
                s3.y  += ring[(i + 1) & 15].y - ring[(i - 2) & 15].y;
                s7.x  += ring[(i + 3) & 15].x - ring[(i - 4) & 15].x;
                s7.y  += ring[(i + 3) & 15].y - ring[(i - 4) & 15].y;
                s15.x += nv.x               - ring[(i - 8) & 15].x;
                s15.y += nv.y               - ring[(i - 8) & 15].y;
                const float2 s1 = ring[i & 15];
                const float ox = s1.x + s3.x * w3 + s7.x * w7 + s15.x * w15;
                const float oy = s1.y + s3.y * w3 + s7.y * w7 + s15.y * w15;
                oA[(size_t)l * H2] = __floats2half2_rn(ox, oy);
            }
        }
    } else {
        for (int l = s0; l < s0 + SL; ++l) {
            float2 s3 = {0.f, 0.f}, s7 = {0.f, 0.f}, s15 = {0.f, 0.f};
            #pragma unroll
            for (int j = -7; j <= 7; ++j) {
                const int p = l + j;
                float2 v = {0.f, 0.f};
                if (p >= 0 && p < L) v = __half22float2(base[(size_t)p * H2]);
                s15.x += v.x; s15.y += v.y;
                if (j >= -3 && j <= 3) { s7.x += v.x; s7.y += v.y; }
                if (j >= -1 && j <= 1) { s3.x += v.x; s3.y += v.y; }
            }
            const float2 s1 = __half22float2(base[(size_t)l * H2]);
            const float c3  = 1.0f / (float)(min(l + 2, L) - max(l - 1, 0));
            const float c7  = 1.0f / (float)(min(l + 4, L) - max(l - 3, 0));
            const float c15 = 1.0f / (float)(min(l + 8, L) - max(l - 7, 0));
            const float ox = s1.x + SW3 * s3.x * c3 + SW7 * s7.x * c7 + SW15 * s15.x * c15;
            const float oy = s1.y + SW3 * s3.y * c3 + SW7 * s7.y * c7 + SW15 * s15.y * c15;
            oA[(size_t)l * H2] = __floats2half2_rn(ox, oy);
        }
    }
}

// ---------------------------------------------------------------------------
// LN2 + residual: 4 rows per block, batched dual reductions
// ---------------------------------------------------------------------------
__global__ __launch_bounds__(256) void ln2_res_kernel(
    const __half* __restrict__ Y, const float* __restrict__ X,
    const float* __restrict__ g, const float* __restrict__ bvec,
    float* __restrict__ out)
{
    __shared__ float sbuf[144];
    const int row0 = blockIdx.x * RPB;
    const int c = threadIdx.x * 4;

    const float4 gv = __ldg((const float4*)(g + c));
    const float4 bv = __ldg((const float4*)(bvec + c));

    float y[RPB][4];
    float v8[8];
    #pragma unroll
    for (int r = 0; r < RPB; ++r) {
        const uint2 yraw = *(const uint2*)(Y + (size_t)(row0 + r) * HD + c);
        const float2 ya = __half22float2(*(const __half2*)&yraw.x);
        const float2 yb = __half22float2(*(const __half2*)&yraw.y);
        y[r][0] = ya.x; y[r][1] = ya.y; y[r][2] = yb.x; y[r][3] = yb.y;
        v8[r]       = ya.x + ya.y + yb.x + yb.y;
        v8[RPB + r] = ya.x * ya.x + ya.y * ya.y + yb.x * yb.x + yb.y * yb.y;
    }
    blk_reduceN<8>(v8, sbuf);

    #pragma unroll
    for (int r = 0; r < RPB; ++r) {
        const float mu   = v8[r] * (1.0f / HD);
        const float var  = v8[RPB + r] * (1.0f / HD) - mu * mu;
        const float rstd = rsqrtf(var + 1e-5f);
        const float4 xv = *(const float4*)(X + (size_t)(row0 + r) * HD + c);
        float4 o;
        o.x = (y[r][0] - mu) * rstd * gv.x + bv.x + xv.x;
        o.y = (y[r][1] - mu) * rstd * gv.y + bv.y + xv.y;
        o.z = (y[r][2] - mu) * rstd * gv.z + bv.z + xv.z;
        o.w = (y[r][3] - mu) * rstd * gv.w + bv.w + xv.w;
        *(float4*)(out + (size_t)(row0 + r) * HD + c) = o;
    }
}

// ---------------------------------------------------------------------------
// Launcher
// ---------------------------------------------------------------------------
extern "C" void kernel_launch(void* const* d_in, const int* in_sizes, int n_in,
                              void* d_out, int out_size)
{
    const float* X   = (const float*)d_in[0];
    const float* msk = (const float*)d_in[1];
    const float* emb = (const float*)d_in[2];
    const float* ltw = (const float*)d_in[3];
    const float* ltb = (const float*)d_in[4];
    const float* g1  = (const float*)d_in[5];
    const float* b1  = (const float*)d_in[6];
    const float* ftw = (const float*)d_in[7];
    const float* ftb = (const float*)d_in[8];
    const float* g2  = (const float*)d_in[9];
    const float* b2  = (const float*)d_in[10];
    float* out = (float*)d_out;

    float *bufA, *bufB;
    __half *A2, *Wt1, *Wt2;
    cudaGetSymbolAddress((void**)&bufA, g_bufA);
    cudaGetSymbolAddress((void**)&bufB, g_bufB);
    cudaGetSymbolAddress((void**)&A2,  g_A2);
    cudaGetSymbolAddress((void**)&Wt1, g_Wt1);
    cudaGetSymbolAddress((void**)&Wt2, g_Wt2);
    __half* Y1h = (__half*)bufA;              // fp16 Y1
    __half* Fh  = (__half*)bufB;              // fp16 F
    __half* Y2h = (__half*)bufB + (size_t)MROWS * HD / 2;  // fp16 Y2 (2nd half)

    cudaFuncSetAttribute((const void*)gemm_mma_kernel<float>,
                         cudaFuncAttributeMaxDynamicSharedMemorySize, GEMM_SMEM);
    cudaFuncSetAttribute((const void*)gemm_mma_kernel<__half>,
                         cudaFuncAttributeMaxDynamicSharedMemorySize, GEMM_SMEM);

    const dim3 ggrid(HD / BN, MROWS / (2 * BM));   // (8, 128) = 1024 CTAs

    // both weight transposes in one launch
    convW2_kernel<<<2 * (HD * HD) / 256, 256>>>(ltw, Wt1, ftw, Wt2);

    // 1) Y1 = X @ lt_w + lt_b   (fp16 out)
    convA_kernel<<<(MROWS * HD / 4) / 256, 256>>>(X, A2);
    gemm_mma_kernel<__half><<<ggrid, 128, GEMM_SMEM>>>(A2, Wt1, ltb, Y1h);
    // 2) F = fusion(LN1(Y1)) -> fp16, 4 rows/block
    ln1_fusion_kernel<<<MROWS / RPB, 256>>>(Y1h, msk, emb, g1, b1, Fh);
    // 3) agg = multiscale(F), half2-vectorized, fp16 in/out -> A2
    multiscale_kernel<<<(BDIM * H2 * 32) / 256, 256>>>(
        (const __half2*)Fh, (__half2*)A2);
    // 4) Y2 = agg @ ft_w + ft_b  (fp16 out)
    gemm_mma_kernel<__half><<<ggrid, 128, GEMM_SMEM>>>(A2, Wt2, ftb, Y2h);
    // 5) out = LN2(Y2) + X
    ln2_res_kernel<<<MROWS / RPB, 256>>>(Y2h, X, g2, b2, out);
}